// round 5
// baseline (speedup 1.0000x reference)
#include <cuda_runtime.h>
#include <math.h>

// ---------------- problem constants ----------------
#define BB   512
#define TT   256
#define HH   256
#define PP   61
#define TBARS 16
#define NPBN 16
#define LATD 512
#define DECD 32
#define KTOT (HH + PP)   // 317

// d_out layout: notes | z | mu | log_var
#define N_NOTES (BB*TT*PP)
#define N_Z     (BB*TT*DECD)
#define N_MU    (BB*TT*LATD)
#define OFF_NOTES 0
#define OFF_Z   ((size_t)N_NOTES)
#define OFF_MU  (OFF_Z + (size_t)N_Z)
#define OFF_LV  (OFF_MU + (size_t)N_MU)

#define FULLMASK 0xffffffffu

// ---------------- scratch (__device__ globals; no allocs allowed) ----------------
__device__ float g_yf[(size_t)BB*TT*HH];       // fwd encoder outputs (B,T,H)
__device__ float g_yb[(size_t)BB*TT*HH];       // bwd encoder outputs, stored un-reversed (B,T,H)
__device__ float g_h[2][2][BB*HH];             // [dir][parity]
__device__ float g_c[2][BB*HH];                // [dir]
__device__ float g_emb[BB*TBARS*DECD];         // conductor embedding (B,TB,DEC)

__device__ __forceinline__ float sigf(float x)   { return 1.f / (1.f + __expf(-x)); }
__device__ __forceinline__ float tanhf_(float x) { return 2.f / (1.f + __expf(-2.f * x)) - 1.f; }

// ---------------- init: zero encoder states ----------------
__global__ void k_init() {
    int i = blockIdx.x * blockDim.x + threadIdx.x;
    if (i < BB*HH) {
        g_h[0][0][i] = 0.f;
        g_h[1][0][i] = 0.f;
        g_c[0][i] = 0.f;
        g_c[1][i] = 0.f;
    }
}

// ---------------- encoder step: both directions, fused LSTM cell ----------------
// grid (8,8,2): (batch/64, hidden/32, dir). 256 threads.
__global__ void __launch_bounds__(256) k_enc_step(
    const float* __restrict__ x,
    const float* __restrict__ WihF, const float* __restrict__ WhhF, const float* __restrict__ bF,
    const float* __restrict__ WihB, const float* __restrict__ WhhB, const float* __restrict__ bB,
    int t)
{
    const int dir = blockIdx.z;
    const int par = t & 1;
    const float* Wih  = dir ? WihB : WihF;
    const float* Whh  = dir ? WhhB : WhhF;
    const float* bias = dir ? bB   : bF;
    const int t_x = dir ? (TT - 1 - t) : t;
    const float* h_in  = g_h[dir][par];
    float*       h_out = g_h[dir][par ^ 1];
    float*       cbuf  = g_c[dir];
    float*       ybuf  = dir ? g_yb : g_yf;

    __shared__ float As[16][64];    // [k][m]
    __shared__ float Bs[16][128];   // [k][gatecol]

    const int tid = threadIdx.x;
    const int b0 = blockIdx.x * 64;
    const int n0 = blockIdx.y * 32;
    const int tx = tid & 15;   // hidden pair
    const int ty = tid >> 4;   // batch quad

    float acc[4][4][2];
#pragma unroll
    for (int g = 0; g < 4; g++)
#pragma unroll
        for (int i = 0; i < 4; i++) { acc[g][i][0] = 0.f; acc[g][i][1] = 0.f; }

    const int am = tid >> 2;
    const int ak = (tid & 3) * 4;
    const int bc = tid >> 1;
    const int bk = (tid & 1) * 8;
    const int bj = (bc >> 5) * HH + n0 + (bc & 31);   // weight row

    for (int k0 = 0; k0 < 320; k0 += 16) {
#pragma unroll
        for (int u = 0; u < 4; u++) {
            int kg = k0 + ak + u;
            float v = 0.f;
            if (kg < HH)        v = h_in[(b0 + am) * HH + kg];
            else if (kg < KTOT) v = x[((size_t)(b0 + am) * TT + t_x) * PP + (kg - HH)];
            As[ak + u][am] = v;
        }
#pragma unroll
        for (int u = 0; u < 8; u++) {
            int kg = k0 + bk + u;
            float v = 0.f;
            if (kg < HH)        v = Whh[(size_t)bj * HH + kg];
            else if (kg < KTOT) v = Wih[(size_t)bj * PP + (kg - HH)];
            Bs[bk + u][bc] = v;
        }
        __syncthreads();
#pragma unroll
        for (int kk = 0; kk < 16; kk++) {
            float4 a4 = *reinterpret_cast<const float4*>(&As[kk][ty * 4]);
            float a[4] = {a4.x, a4.y, a4.z, a4.w};
#pragma unroll
            for (int g = 0; g < 4; g++) {
                float2 b2 = *reinterpret_cast<const float2*>(&Bs[kk][g * 32 + tx * 2]);
#pragma unroll
                for (int i = 0; i < 4; i++) {
                    acc[g][i][0] = fmaf(a[i], b2.x, acc[g][i][0]);
                    acc[g][i][1] = fmaf(a[i], b2.y, acc[g][i][1]);
                }
            }
        }
        __syncthreads();
    }

#pragma unroll
    for (int i = 0; i < 4; i++) {
        int bm = b0 + ty * 4 + i;
#pragma unroll
        for (int j = 0; j < 2; j++) {
            int n = n0 + tx * 2 + j;
            float gi = acc[0][i][j] + bias[n];
            float gf = acc[1][i][j] + bias[HH + n];
            float gg = acc[2][i][j] + bias[2 * HH + n];
            float go = acc[3][i][j] + bias[3 * HH + n];
            float cold = cbuf[bm * HH + n];
            float cn = sigf(gf) * cold + sigf(gi) * tanhf_(gg);
            float hn = sigf(go) * tanhf_(cn);
            cbuf[bm * HH + n]  = cn;
            h_out[bm * HH + n] = hn;
            ybuf[((size_t)bm * TT + t_x) * HH + n] = hn;
        }
    }
}

// ---------------- enc @ Wout^T + bout, split mu / softplus(log_var) ----------------
// M=131072, N=1024, K=512. A = [y_f | y_b]. 128x128x16 tiles, 8x8 per thread.
__global__ void __launch_bounds__(256) k_wout(
    const float* __restrict__ Wout, const float* __restrict__ bout,
    float* __restrict__ out)
{
    __shared__ float As[16][128];
    __shared__ float Bs[16][128];
    const int tid = threadIdx.x;
    const size_t m0 = (size_t)blockIdx.x * 128;
    const int n0 = blockIdx.y * 128;
    const int tx = tid & 15;
    const int ty = tid >> 4;

    float acc[8][8];
#pragma unroll
    for (int i = 0; i < 8; i++)
#pragma unroll
        for (int j = 0; j < 8; j++) acc[i][j] = 0.f;

    const int am = tid >> 1;
    const int ak = (tid & 1) * 8;
    const int bn = tid >> 1;
    const int bk = (tid & 1) * 8;

    for (int kt = 0; kt < 32; kt++) {
        const float* srcA = (kt < 16) ? g_yf : g_yb;
        int koff = (kt & 15) * 16;
        const float4* ap = reinterpret_cast<const float4*>(
            &srcA[(m0 + am) * HH + koff + ak]);
        float4 a0 = ap[0], a1 = ap[1];
        As[ak + 0][am] = a0.x; As[ak + 1][am] = a0.y; As[ak + 2][am] = a0.z; As[ak + 3][am] = a0.w;
        As[ak + 4][am] = a1.x; As[ak + 5][am] = a1.y; As[ak + 6][am] = a1.z; As[ak + 7][am] = a1.w;

        const float4* bp = reinterpret_cast<const float4*>(
            &Wout[(size_t)(n0 + bn) * 512 + (kt & 15) * 16 + ((kt < 16) ? 0 : 256) + bk]);
        float4 b0 = bp[0], b1 = bp[1];
        Bs[bk + 0][bn] = b0.x; Bs[bk + 1][bn] = b0.y; Bs[bk + 2][bn] = b0.z; Bs[bk + 3][bn] = b0.w;
        Bs[bk + 4][bn] = b1.x; Bs[bk + 5][bn] = b1.y; Bs[bk + 6][bn] = b1.z; Bs[bk + 7][bn] = b1.w;
        __syncthreads();
#pragma unroll
        for (int kk = 0; kk < 16; kk++) {
            float4 a4a = *reinterpret_cast<const float4*>(&As[kk][ty * 8]);
            float4 a4b = *reinterpret_cast<const float4*>(&As[kk][ty * 8 + 4]);
            float4 b4a = *reinterpret_cast<const float4*>(&Bs[kk][tx * 8]);
            float4 b4b = *reinterpret_cast<const float4*>(&Bs[kk][tx * 8 + 4]);
            float a[8] = {a4a.x, a4a.y, a4a.z, a4a.w, a4b.x, a4b.y, a4b.z, a4b.w};
            float b[8] = {b4a.x, b4a.y, b4a.z, b4a.w, b4b.x, b4b.y, b4b.z, b4b.w};
#pragma unroll
            for (int i = 0; i < 8; i++)
#pragma unroll
                for (int j = 0; j < 8; j++)
                    acc[i][j] = fmaf(a[i], b[j], acc[i][j]);
        }
        __syncthreads();
    }

#pragma unroll
    for (int i = 0; i < 8; i++) {
        size_t m = m0 + ty * 8 + i;
#pragma unroll
        for (int j = 0; j < 8; j++) {
            int n = n0 + tx * 8 + j;
            float v = acc[i][j] + bout[n];
            if (n < 512) {
                out[OFF_MU + m * 512 + n] = v;
            } else {
                float a2 = fabsf(v);
                float sp = fmaxf(v, 0.f) + log1pf(__expf(-a2));
                out[OFF_LV + m * 512 + (n - 512)] = sp;
            }
        }
    }
}

// ---------------- z = (mu + eps*exp(2*lv)) @ Wz^T + bz ----------------
__global__ void __launch_bounds__(256) k_z(
    const float* __restrict__ eps, const float* __restrict__ Wz, const float* __restrict__ bz,
    float* out)
{
    __shared__ float ZL[64 * 65];
    __shared__ float WZs[32 * 65];
    const int tid = threadIdx.x;
    const size_t m0 = (size_t)blockIdx.x * 64;
    const int tx = tid & 15;
    const int ty = tid >> 4;
    const float* mu = out + OFF_MU;
    const float* lv = out + OFF_LV;

    float acc[4][2];
#pragma unroll
    for (int r = 0; r < 4; r++) { acc[r][0] = 0.f; acc[r][1] = 0.f; }

    const int lm = tid >> 2;
    const int lk = (tid & 3) * 16;
    const int wn = tid >> 3;
    const int wk = (tid & 7) * 8;

    for (int kt = 0; kt < 8; kt++) {
        int kb = kt * 64;
        size_t rowg = m0 + lm;
        int b = (int)(rowg >> 8);
#pragma unroll
        for (int u = 0; u < 16; u++) {
            int kg = kb + lk + u;
            float m_ = mu[rowg * 512 + kg];
            float l_ = lv[rowg * 512 + kg];
            ZL[lm * 65 + lk + u] = m_ + eps[b * 512 + kg] * __expf(2.f * l_);
        }
#pragma unroll
        for (int u = 0; u < 8; u++)
            WZs[wn * 65 + wk + u] = Wz[wn * 512 + kb + wk + u];
        __syncthreads();
#pragma unroll 4
        for (int kk = 0; kk < 64; kk++) {
            float w0 = WZs[(tx * 2) * 65 + kk];
            float w1 = WZs[(tx * 2 + 1) * 65 + kk];
#pragma unroll
            for (int r = 0; r < 4; r++) {
                float zv = ZL[(ty * 4 + r) * 65 + kk];
                acc[r][0] = fmaf(zv, w0, acc[r][0]);
                acc[r][1] = fmaf(zv, w1, acc[r][1]);
            }
        }
        __syncthreads();
    }
#pragma unroll
    for (int r = 0; r < 4; r++)
#pragma unroll
        for (int j = 0; j < 2; j++) {
            int n = tx * 2 + j;
            out[OFF_Z + (m0 + ty * 4 + r) * DECD + n] = acc[r][j] + bz[n];
        }
}

// ---------------- conductor LSTM: 16 steps in one kernel ----------------
__global__ void __launch_bounds__(1024) k_conductor(
    const float* __restrict__ Wih, const float* __restrict__ Whh, const float* __restrict__ bias,
    const float* __restrict__ out)
{
    __shared__ float sWi[128 * 33], sWh[128 * 33], sb[128];
    __shared__ float hs[32 * 33], zs[32 * 33];
    int tid = threadIdx.x;
    for (int i = tid; i < 128 * 32; i += 1024) {
        sWi[(i >> 5) * 33 + (i & 31)] = Wih[i];
        sWh[(i >> 5) * 33 + (i & 31)] = Whh[i];
    }
    if (tid < 128) sb[tid] = bias[tid];
    int row = tid >> 5, n = tid & 31;
    hs[row * 33 + n] = 0.f;
    float c = 0.f;
    int bglob = blockIdx.x * 32 + row;
    const float* z = out + OFF_Z;
    __syncthreads();
    for (int t = 0; t < TBARS; t++) {
        zs[row * 33 + n] = z[((size_t)bglob * TT + t) * DECD + n];
        __syncthreads();
        float a0 = sb[n], a1 = sb[32 + n], a2 = sb[64 + n], a3 = sb[96 + n];
#pragma unroll
        for (int k = 0; k < 32; k++) {
            float hk = hs[row * 33 + k], zk = zs[row * 33 + k];
            a0 = fmaf(hk, sWh[n * 33 + k],        fmaf(zk, sWi[n * 33 + k],        a0));
            a1 = fmaf(hk, sWh[(32 + n) * 33 + k], fmaf(zk, sWi[(32 + n) * 33 + k], a1));
            a2 = fmaf(hk, sWh[(64 + n) * 33 + k], fmaf(zk, sWi[(64 + n) * 33 + k], a2));
            a3 = fmaf(hk, sWh[(96 + n) * 33 + k], fmaf(zk, sWi[(96 + n) * 33 + k], a3));
        }
        c = sigf(a1) * c + sigf(a0) * tanhf_(a2);
        float h = sigf(a3) * tanhf_(c);
        __syncthreads();
        hs[row * 33 + n] = h;
        g_emb[((size_t)bglob * TBARS + t) * DECD + n] = h;
        __syncthreads();
    }
}

// ---------------- decoder: one warp per (batch, bar) row, 16 steps + softmax ----------------
__global__ void __launch_bounds__(256) k_decoder(
    const float* __restrict__ x, const float* __restrict__ dh0, const float* __restrict__ dc0,
    const float* __restrict__ Wih, const float* __restrict__ Whh, const float* __restrict__ bg,
    const float* __restrict__ Wlin, const float* __restrict__ blin, float* __restrict__ out)
{
    extern __shared__ float sm[];
    float* sWih = sm;                 // 128*97
    float* sWhh = sWih + 128 * 97;    // 128*33
    float* sWl  = sWhh + 128 * 33;    // 64*33
    float* sbg  = sWl + 64 * 33;      // 128
    float* sbl  = sbg + 128;          // 64
    float* sx   = sbl + 64;           // 8*64
    int tid = threadIdx.x;
    for (int i = tid; i < 128 * 93; i += 256) sWih[(i / 93) * 97 + (i % 93)] = Wih[i];
    for (int i = tid; i < 128 * 32; i += 256) sWhh[(i >> 5) * 33 + (i & 31)] = Whh[i];
    for (int i = tid; i < 61 * 32;  i += 256) sWl[(i >> 5) * 33 + (i & 31)] = Wlin[i];
    if (tid < 128) sbg[tid] = bg[tid];
    if (tid < 64)  sbl[tid] = (tid < 61) ? blin[tid] : 0.f;
    __syncthreads();

    int w = tid >> 5, n = tid & 31;
    int r = blockIdx.x * 8 + w;
    int b = r >> 4, bar = r & 15;
    float h  = dh0[(size_t)bar * BB * DECD + b * DECD + n];
    float c  = dc0[(size_t)bar * BB * DECD + b * DECD + n];
    float ev = g_emb[((size_t)b * TBARS + bar) * DECD + n];
    float* xw = sx + w * 64;

    const float* w0 = sWih + (size_t)n * 97;
    const float* w1 = sWih + (size_t)(32 + n) * 97;
    const float* w2 = sWih + (size_t)(64 + n) * 97;
    const float* w3 = sWih + (size_t)(96 + n) * 97;
    const float* u0 = sWhh + (size_t)n * 33;
    const float* u1 = sWhh + (size_t)(32 + n) * 33;
    const float* u2 = sWhh + (size_t)(64 + n) * 33;
    const float* u3 = sWhh + (size_t)(96 + n) * 33;
    bool has1 = (n < 29);

    for (int t = 0; t < NPBN; t++) {
        int tau = bar * NPBN + t;
        float v0 = 0.f, v1 = 0.f;
        if (tau > 0) {
            size_t base = ((size_t)b * TT + (tau - 1)) * PP;
            v0 = x[base + n];
            if (has1) v1 = x[base + n + 32];
        }
        xw[n] = v0;
        if (has1) xw[n + 32] = v1;
        __syncwarp();

        float a0 = sbg[n], a1 = sbg[32 + n], a2 = sbg[64 + n], a3 = sbg[96 + n];
#pragma unroll
        for (int k = 0; k < 32; k++) {
            float e_ = __shfl_sync(FULLMASK, ev, k);
            a0 = fmaf(e_, w0[k], a0); a1 = fmaf(e_, w1[k], a1);
            a2 = fmaf(e_, w2[k], a2); a3 = fmaf(e_, w3[k], a3);
        }
#pragma unroll
        for (int k = 0; k < PP; k++) {
            float xv = xw[k];
            a0 = fmaf(xv, w0[32 + k], a0); a1 = fmaf(xv, w1[32 + k], a1);
            a2 = fmaf(xv, w2[32 + k], a2); a3 = fmaf(xv, w3[32 + k], a3);
        }
#pragma unroll
        for (int k = 0; k < 32; k++) {
            float hk = __shfl_sync(FULLMASK, h, k);
            a0 = fmaf(hk, u0[k], a0); a1 = fmaf(hk, u1[k], a1);
            a2 = fmaf(hk, u2[k], a2); a3 = fmaf(hk, u3[k], a3);
        }
        c = sigf(a1) * c + sigf(a0) * tanhf_(a2);
        h = sigf(a3) * tanhf_(c);

        float l0 = sbl[n];
        float l1 = has1 ? sbl[n + 32] : -1e30f;
#pragma unroll
        for (int k = 0; k < 32; k++) {
            float hk = __shfl_sync(FULLMASK, h, k);
            l0 = fmaf(hk, sWl[n * 33 + k], l0);
            if (has1) l1 = fmaf(hk, sWl[(n + 32) * 33 + k], l1);
        }
        float m = fmaxf(l0, l1);
#pragma unroll
        for (int o = 16; o > 0; o >>= 1) m = fmaxf(m, __shfl_xor_sync(FULLMASK, m, o));
        float e0 = __expf(l0 - m);
        float e1 = has1 ? __expf(l1 - m) : 0.f;
        float s = e0 + e1;
#pragma unroll
        for (int o = 16; o > 0; o >>= 1) s += __shfl_xor_sync(FULLMASK, s, o);
        float inv = 1.f / s;
        size_t ob = OFF_NOTES + ((size_t)b * TT + tau) * PP;
        out[ob + n] = e0 * inv;
        if (has1) out[ob + n + 32] = e1 * inv;
        __syncwarp();
    }
}

// ---------------- launch ----------------
extern "C" void kernel_launch(void* const* d_in, const int* in_sizes, int n_in,
                              void* d_out, int out_size) {
    const float* x    = (const float*)d_in[0];
    const float* eps  = (const float*)d_in[1];
    const float* dh0  = (const float*)d_in[2];
    const float* dc0  = (const float*)d_in[3];
    const float* eWif = (const float*)d_in[4];
    const float* eWhf = (const float*)d_in[5];
    const float* ebf  = (const float*)d_in[6];
    const float* eWib = (const float*)d_in[7];
    const float* eWhb = (const float*)d_in[8];
    const float* ebb  = (const float*)d_in[9];
    const float* Wout = (const float*)d_in[10];
    const float* bout = (const float*)d_in[11];
    const float* Wz   = (const float*)d_in[12];
    const float* bz   = (const float*)d_in[13];
    const float* cWi  = (const float*)d_in[14];
    const float* cWh  = (const float*)d_in[15];
    const float* cb   = (const float*)d_in[16];
    const float* dWi  = (const float*)d_in[17];
    const float* dWh  = (const float*)d_in[18];
    const float* db   = (const float*)d_in[19];
    const float* Wlin = (const float*)d_in[20];
    const float* blin = (const float*)d_in[21];
    float* out = (float*)d_out;

    cudaFuncSetAttribute(k_decoder, cudaFuncAttributeMaxDynamicSharedMemorySize, 77824);

    k_init<<<512, 256>>>();
    dim3 eg(8, 8, 2);
    for (int t = 0; t < TT; t++)
        k_enc_step<<<eg, 256>>>(x, eWif, eWhf, ebf, eWib, eWhb, ebb, t);
    k_wout<<<dim3(1024, 8), 256>>>(Wout, bout, out);
    k_z<<<2048, 256>>>(eps, Wz, bz, out);
    k_conductor<<<16, 1024>>>(cWi, cWh, cb, out);
    k_decoder<<<1024, 256, 77824>>>(x, dh0, dc0, dWi, dWh, db, Wlin, blin, out);
}

// round 6
// speedup vs baseline: 1.3751x; 1.3751x over previous
#include <cuda_runtime.h>
#include <math.h>

// ---------------- problem constants ----------------
#define BB   512
#define TT   256
#define HH   256
#define PP   61
#define TBARS 16
#define NPBN 16
#define LATD 512
#define DECD 32
#define KTOT (HH + PP)   // 317

// d_out layout: notes | z | mu | log_var
#define N_NOTES (BB*TT*PP)
#define N_Z     (BB*TT*DECD)
#define N_MU    (BB*TT*LATD)
#define OFF_NOTES 0
#define OFF_Z   ((size_t)N_NOTES)
#define OFF_MU  (OFF_Z + (size_t)N_Z)
#define OFF_LV  (OFF_MU + (size_t)N_MU)

#define FULLMASK 0xffffffffu

// ---------------- scratch (__device__ globals; no allocs allowed) ----------------
__device__ float g_yf[(size_t)BB*TT*HH];       // fwd encoder outputs (B,T,H)
__device__ float g_yb[(size_t)BB*TT*HH];       // bwd encoder outputs, stored un-reversed (B,T,H)
__device__ float g_h[2][2][BB*HH];             // [dir][parity]
__device__ float g_emb[BB*TBARS*DECD];         // conductor embedding (B,TB,DEC)
__device__ unsigned g_ctr[2];                  // per-direction step barrier counters

__device__ __forceinline__ float sigf(float x)   { return 1.f / (1.f + __expf(-x)); }
__device__ __forceinline__ float tanhf_(float x) { return 2.f / (1.f + __expf(-2.f * x)) - 1.f; }

// ---------------- init: zero encoder state + barrier counters ----------------
__global__ void k_init() {
    int i = blockIdx.x * blockDim.x + threadIdx.x;
    if (i < BB*HH) {
        g_h[0][0][i] = 0.f;
        g_h[1][0][i] = 0.f;
    }
    if (i < 2) g_ctr[i] = 0u;
}

// ---------------- persistent encoder: weights resident in smem, 256 steps in-kernel ----------------
// grid (8,8,2): (batch/64, hidden/32, dir). 256 threads. 1 block/SM (172KB smem), all resident.
#define SW_ELEMS (320 * 128)
#define SA_STRIDE 68
#define ENC_SMEM ((SW_ELEMS + 32 * SA_STRIDE) * 4)

__global__ void __launch_bounds__(256) k_enc_persist(
    const float* __restrict__ x,
    const float* __restrict__ WihF, const float* __restrict__ WhhF, const float* __restrict__ bF,
    const float* __restrict__ WihB, const float* __restrict__ WhhB, const float* __restrict__ bB)
{
    extern __shared__ float sm[];
    float* sW = sm;                 // [k 0..319][col 0..127]
    float* sA = sm + SW_ELEMS;      // [k 0..31][m 0..63] stride 68

    const int dir = blockIdx.z;
    const float* Wih  = dir ? WihB : WihF;
    const float* Whh  = dir ? WhhB : WhhF;
    const float* bias = dir ? bB   : bF;
    float* ybuf = dir ? g_yb : g_yf;

    const int tid = threadIdx.x;
    const int b0 = blockIdx.x * 64;
    const int n0 = blockIdx.y * 32;
    const int tx = tid & 15;   // hidden pair
    const int ty = tid >> 4;   // batch quad

    // ---- load this block's weight tile into smem (once) ----
    for (int idx = tid; idx < SW_ELEMS; idx += 256) {
        int c = idx / 320;
        int k = idx - c * 320;
        int bj = (c >> 5) * HH + n0 + (c & 31);
        float v = 0.f;
        if (k < HH)        v = Whh[(size_t)bj * HH + k];
        else if (k < KTOT) v = Wih[(size_t)bj * PP + (k - HH)];
        sW[k * 128 + c] = v;
    }

    // bias in registers
    float bias_r[4][2];
#pragma unroll
    for (int g = 0; g < 4; g++)
#pragma unroll
        for (int j = 0; j < 2; j++)
            bias_r[g][j] = bias[g * HH + n0 + tx * 2 + j];

    // cell state in registers for the whole sequence (block-private)
    float cst[4][2];
#pragma unroll
    for (int i = 0; i < 4; i++) { cst[i][0] = 0.f; cst[i][1] = 0.f; }

    // A-chunk loader coords
    const int lm = tid >> 2;            // 0..63
    const int lkq = (tid & 3) * 8;      // 0,8,16,24

    __syncthreads();

    volatile unsigned* vctr = &g_ctr[dir];

    for (int t = 0; t < TT; t++) {
        const int par = t & 1;
        const float* h_in  = g_h[dir][par];
        float*       h_out = g_h[dir][par ^ 1];
        const int t_x = dir ? (TT - 1 - t) : t;

        float acc[4][4][2];
#pragma unroll
        for (int g = 0; g < 4; g++)
#pragma unroll
            for (int i = 0; i < 4; i++) { acc[g][i][0] = 0.f; acc[g][i][1] = 0.f; }

        for (int ch = 0; ch < 10; ch++) {
            const int k0 = ch * 32;
            // stage A chunk: 64 batch x 32 k
            if (ch < 8) {
                const float4* p = reinterpret_cast<const float4*>(
                    h_in + (size_t)(b0 + lm) * HH + k0 + lkq);
                float4 v0 = __ldcg(p);
                float4 v1 = __ldcg(p + 1);
                float vv[8] = {v0.x, v0.y, v0.z, v0.w, v1.x, v1.y, v1.z, v1.w};
#pragma unroll
                for (int u = 0; u < 8; u++) sA[(lkq + u) * SA_STRIDE + lm] = vv[u];
            } else {
                size_t xb = ((size_t)(b0 + lm) * TT + t_x) * PP;
#pragma unroll
                for (int u = 0; u < 8; u++) {
                    int kg = k0 + lkq + u - HH;
                    sA[(lkq + u) * SA_STRIDE + lm] = (kg < PP) ? x[xb + kg] : 0.f;
                }
            }
            __syncthreads();
#pragma unroll 8
            for (int kk = 0; kk < 32; kk++) {
                float4 a4 = *reinterpret_cast<const float4*>(&sA[kk * SA_STRIDE + ty * 4]);
                float a[4] = {a4.x, a4.y, a4.z, a4.w};
                const float* wrow = &sW[(size_t)(k0 + kk) * 128];
#pragma unroll
                for (int g = 0; g < 4; g++) {
                    float2 b2 = *reinterpret_cast<const float2*>(&wrow[g * 32 + tx * 2]);
#pragma unroll
                    for (int i = 0; i < 4; i++) {
                        acc[g][i][0] = fmaf(a[i], b2.x, acc[g][i][0]);
                        acc[g][i][1] = fmaf(a[i], b2.y, acc[g][i][1]);
                    }
                }
            }
            __syncthreads();
        }

        // ---- fused LSTM cell epilogue ----
#pragma unroll
        for (int i = 0; i < 4; i++) {
            int bm = b0 + ty * 4 + i;
#pragma unroll
            for (int j = 0; j < 2; j++) {
                int n = n0 + tx * 2 + j;
                float gi = acc[0][i][j] + bias_r[0][j];
                float gf = acc[1][i][j] + bias_r[1][j];
                float gg = acc[2][i][j] + bias_r[2][j];
                float go = acc[3][i][j] + bias_r[3][j];
                float cn = sigf(gf) * cst[i][j] + sigf(gi) * tanhf_(gg);
                cst[i][j] = cn;
                float hn = sigf(go) * tanhf_(cn);
                h_out[(size_t)bm * HH + n] = hn;
                ybuf[((size_t)bm * TT + t_x) * HH + n] = hn;
            }
        }

        // ---- grid barrier (per direction, monotonic counter) ----
        __threadfence();
        __syncthreads();
        if (tid == 0) {
            atomicAdd(&g_ctr[dir], 1u);
            unsigned target = (unsigned)(t + 1) * 64u;
            while (*vctr < target) { }
            __threadfence();
        }
        __syncthreads();
    }
}

// ---------------- enc @ Wout^T + bout, split mu / softplus(log_var) ----------------
// M=131072, N=1024, K=512. A = [y_f | y_b]. 128x128x16 tiles, 8x8 per thread.
__global__ void __launch_bounds__(256) k_wout(
    const float* __restrict__ Wout, const float* __restrict__ bout,
    float* __restrict__ out)
{
    __shared__ float As[16][128];
    __shared__ float Bs[16][128];
    const int tid = threadIdx.x;
    const size_t m0 = (size_t)blockIdx.x * 128;
    const int n0 = blockIdx.y * 128;
    const int tx = tid & 15;
    const int ty = tid >> 4;

    float acc[8][8];
#pragma unroll
    for (int i = 0; i < 8; i++)
#pragma unroll
        for (int j = 0; j < 8; j++) acc[i][j] = 0.f;

    const int am = tid >> 1;
    const int ak = (tid & 1) * 8;
    const int bn = tid >> 1;
    const int bk = (tid & 1) * 8;

    for (int kt = 0; kt < 32; kt++) {
        const float* srcA = (kt < 16) ? g_yf : g_yb;
        int koff = (kt & 15) * 16;
        const float4* ap = reinterpret_cast<const float4*>(
            &srcA[(m0 + am) * HH + koff + ak]);
        float4 a0 = ap[0], a1 = ap[1];
        As[ak + 0][am] = a0.x; As[ak + 1][am] = a0.y; As[ak + 2][am] = a0.z; As[ak + 3][am] = a0.w;
        As[ak + 4][am] = a1.x; As[ak + 5][am] = a1.y; As[ak + 6][am] = a1.z; As[ak + 7][am] = a1.w;

        const float4* bp = reinterpret_cast<const float4*>(
            &Wout[(size_t)(n0 + bn) * 512 + (kt & 15) * 16 + ((kt < 16) ? 0 : 256) + bk]);
        float4 b0 = bp[0], b1 = bp[1];
        Bs[bk + 0][bn] = b0.x; Bs[bk + 1][bn] = b0.y; Bs[bk + 2][bn] = b0.z; Bs[bk + 3][bn] = b0.w;
        Bs[bk + 4][bn] = b1.x; Bs[bk + 5][bn] = b1.y; Bs[bk + 6][bn] = b1.z; Bs[bk + 7][bn] = b1.w;
        __syncthreads();
#pragma unroll
        for (int kk = 0; kk < 16; kk++) {
            float4 a4a = *reinterpret_cast<const float4*>(&As[kk][ty * 8]);
            float4 a4b = *reinterpret_cast<const float4*>(&As[kk][ty * 8 + 4]);
            float4 b4a = *reinterpret_cast<const float4*>(&Bs[kk][tx * 8]);
            float4 b4b = *reinterpret_cast<const float4*>(&Bs[kk][tx * 8 + 4]);
            float a[8] = {a4a.x, a4a.y, a4a.z, a4a.w, a4b.x, a4b.y, a4b.z, a4b.w};
            float b[8] = {b4a.x, b4a.y, b4a.z, b4a.w, b4b.x, b4b.y, b4b.z, b4b.w};
#pragma unroll
            for (int i = 0; i < 8; i++)
#pragma unroll
                for (int j = 0; j < 8; j++)
                    acc[i][j] = fmaf(a[i], b[j], acc[i][j]);
        }
        __syncthreads();
    }

#pragma unroll
    for (int i = 0; i < 8; i++) {
        size_t m = m0 + ty * 8 + i;
#pragma unroll
        for (int j = 0; j < 8; j++) {
            int n = n0 + tx * 8 + j;
            float v = acc[i][j] + bout[n];
            if (n < 512) {
                out[OFF_MU + m * 512 + n] = v;
            } else {
                float a2 = fabsf(v);
                float sp = fmaxf(v, 0.f) + log1pf(__expf(-a2));
                out[OFF_LV + m * 512 + (n - 512)] = sp;
            }
        }
    }
}

// ---------------- z = (mu + eps*exp(2*lv)) @ Wz^T + bz ----------------
__global__ void __launch_bounds__(256) k_z(
    const float* __restrict__ eps, const float* __restrict__ Wz, const float* __restrict__ bz,
    float* out)
{
    __shared__ float ZL[64 * 65];
    __shared__ float WZs[32 * 65];
    const int tid = threadIdx.x;
    const size_t m0 = (size_t)blockIdx.x * 64;
    const int tx = tid & 15;
    const int ty = tid >> 4;
    const float* mu = out + OFF_MU;
    const float* lv = out + OFF_LV;

    float acc[4][2];
#pragma unroll
    for (int r = 0; r < 4; r++) { acc[r][0] = 0.f; acc[r][1] = 0.f; }

    const int lm = tid >> 2;
    const int lk = (tid & 3) * 16;
    const int wn = tid >> 3;
    const int wk = (tid & 7) * 8;

    for (int kt = 0; kt < 8; kt++) {
        int kb = kt * 64;
        size_t rowg = m0 + lm;
        int b = (int)(rowg >> 8);
#pragma unroll
        for (int u = 0; u < 16; u++) {
            int kg = kb + lk + u;
            float m_ = mu[rowg * 512 + kg];
            float l_ = lv[rowg * 512 + kg];
            ZL[lm * 65 + lk + u] = m_ + eps[b * 512 + kg] * __expf(2.f * l_);
        }
#pragma unroll
        for (int u = 0; u < 8; u++)
            WZs[wn * 65 + wk + u] = Wz[wn * 512 + kb + wk + u];
        __syncthreads();
#pragma unroll 4
        for (int kk = 0; kk < 64; kk++) {
            float w0 = WZs[(tx * 2) * 65 + kk];
            float w1 = WZs[(tx * 2 + 1) * 65 + kk];
#pragma unroll
            for (int r = 0; r < 4; r++) {
                float zv = ZL[(ty * 4 + r) * 65 + kk];
                acc[r][0] = fmaf(zv, w0, acc[r][0]);
                acc[r][1] = fmaf(zv, w1, acc[r][1]);
            }
        }
        __syncthreads();
    }
#pragma unroll
    for (int r = 0; r < 4; r++)
#pragma unroll
        for (int j = 0; j < 2; j++) {
            int n = tx * 2 + j;
            out[OFF_Z + (m0 + ty * 4 + r) * DECD + n] = acc[r][j] + bz[n];
        }
}

// ---------------- conductor LSTM: 16 steps in one kernel ----------------
__global__ void __launch_bounds__(1024) k_conductor(
    const float* __restrict__ Wih, const float* __restrict__ Whh, const float* __restrict__ bias,
    const float* __restrict__ out)
{
    __shared__ float sWi[128 * 33], sWh[128 * 33], sb[128];
    __shared__ float hs[32 * 33], zs[32 * 33];
    int tid = threadIdx.x;
    for (int i = tid; i < 128 * 32; i += 1024) {
        sWi[(i >> 5) * 33 + (i & 31)] = Wih[i];
        sWh[(i >> 5) * 33 + (i & 31)] = Whh[i];
    }
    if (tid < 128) sb[tid] = bias[tid];
    int row = tid >> 5, n = tid & 31;
    hs[row * 33 + n] = 0.f;
    float c = 0.f;
    int bglob = blockIdx.x * 32 + row;
    const float* z = out + OFF_Z;
    __syncthreads();
    for (int t = 0; t < TBARS; t++) {
        zs[row * 33 + n] = z[((size_t)bglob * TT + t) * DECD + n];
        __syncthreads();
        float a0 = sb[n], a1 = sb[32 + n], a2 = sb[64 + n], a3 = sb[96 + n];
#pragma unroll
        for (int k = 0; k < 32; k++) {
            float hk = hs[row * 33 + k], zk = zs[row * 33 + k];
            a0 = fmaf(hk, sWh[n * 33 + k],        fmaf(zk, sWi[n * 33 + k],        a0));
            a1 = fmaf(hk, sWh[(32 + n) * 33 + k], fmaf(zk, sWi[(32 + n) * 33 + k], a1));
            a2 = fmaf(hk, sWh[(64 + n) * 33 + k], fmaf(zk, sWi[(64 + n) * 33 + k], a2));
            a3 = fmaf(hk, sWh[(96 + n) * 33 + k], fmaf(zk, sWi[(96 + n) * 33 + k], a3));
        }
        c = sigf(a1) * c + sigf(a0) * tanhf_(a2);
        float h = sigf(a3) * tanhf_(c);
        __syncthreads();
        hs[row * 33 + n] = h;
        g_emb[((size_t)bglob * TBARS + t) * DECD + n] = h;
        __syncthreads();
    }
}

// ---------------- decoder: one warp per (batch, bar) row, 16 steps + softmax ----------------
__global__ void __launch_bounds__(256) k_decoder(
    const float* __restrict__ x, const float* __restrict__ dh0, const float* __restrict__ dc0,
    const float* __restrict__ Wih, const float* __restrict__ Whh, const float* __restrict__ bg,
    const float* __restrict__ Wlin, const float* __restrict__ blin, float* __restrict__ out)
{
    extern __shared__ float smdec[];
    float* sWih = smdec;              // 128*97
    float* sWhh = sWih + 128 * 97;    // 128*33
    float* sWl  = sWhh + 128 * 33;    // 64*33
    float* sbg  = sWl + 64 * 33;      // 128
    float* sbl  = sbg + 128;          // 64
    float* sx   = sbl + 64;           // 8*64
    int tid = threadIdx.x;
    for (int i = tid; i < 128 * 93; i += 256) sWih[(i / 93) * 97 + (i % 93)] = Wih[i];
    for (int i = tid; i < 128 * 32; i += 256) sWhh[(i >> 5) * 33 + (i & 31)] = Whh[i];
    for (int i = tid; i < 61 * 32;  i += 256) sWl[(i >> 5) * 33 + (i & 31)] = Wlin[i];
    if (tid < 128) sbg[tid] = bg[tid];
    if (tid < 64)  sbl[tid] = (tid < 61) ? blin[tid] : 0.f;
    __syncthreads();

    int w = tid >> 5, n = tid & 31;
    int r = blockIdx.x * 8 + w;
    int b = r >> 4, bar = r & 15;
    float h  = dh0[(size_t)bar * BB * DECD + b * DECD + n];
    float c  = dc0[(size_t)bar * BB * DECD + b * DECD + n];
    float ev = g_emb[((size_t)b * TBARS + bar) * DECD + n];
    float* xw = sx + w * 64;

    const float* w0 = sWih + (size_t)n * 97;
    const float* w1 = sWih + (size_t)(32 + n) * 97;
    const float* w2 = sWih + (size_t)(64 + n) * 97;
    const float* w3 = sWih + (size_t)(96 + n) * 97;
    const float* u0 = sWhh + (size_t)n * 33;
    const float* u1 = sWhh + (size_t)(32 + n) * 33;
    const float* u2 = sWhh + (size_t)(64 + n) * 33;
    const float* u3 = sWhh + (size_t)(96 + n) * 33;
    bool has1 = (n < 29);

    for (int t = 0; t < NPBN; t++) {
        int tau = bar * NPBN + t;
        float v0 = 0.f, v1 = 0.f;
        if (tau > 0) {
            size_t base = ((size_t)b * TT + (tau - 1)) * PP;
            v0 = x[base + n];
            if (has1) v1 = x[base + n + 32];
        }
        xw[n] = v0;
        if (has1) xw[n + 32] = v1;
        __syncwarp();

        float a0 = sbg[n], a1 = sbg[32 + n], a2 = sbg[64 + n], a3 = sbg[96 + n];
#pragma unroll
        for (int k = 0; k < 32; k++) {
            float e_ = __shfl_sync(FULLMASK, ev, k);
            a0 = fmaf(e_, w0[k], a0); a1 = fmaf(e_, w1[k], a1);
            a2 = fmaf(e_, w2[k], a2); a3 = fmaf(e_, w3[k], a3);
        }
#pragma unroll
        for (int k = 0; k < PP; k++) {
            float xv = xw[k];
            a0 = fmaf(xv, w0[32 + k], a0); a1 = fmaf(xv, w1[32 + k], a1);
            a2 = fmaf(xv, w2[32 + k], a2); a3 = fmaf(xv, w3[32 + k], a3);
        }
#pragma unroll
        for (int k = 0; k < 32; k++) {
            float hk = __shfl_sync(FULLMASK, h, k);
            a0 = fmaf(hk, u0[k], a0); a1 = fmaf(hk, u1[k], a1);
            a2 = fmaf(hk, u2[k], a2); a3 = fmaf(hk, u3[k], a3);
        }
        c = sigf(a1) * c + sigf(a0) * tanhf_(a2);
        h = sigf(a3) * tanhf_(c);

        float l0 = sbl[n];
        float l1 = has1 ? sbl[n + 32] : -1e30f;
#pragma unroll
        for (int k = 0; k < 32; k++) {
            float hk = __shfl_sync(FULLMASK, h, k);
            l0 = fmaf(hk, sWl[n * 33 + k], l0);
            if (has1) l1 = fmaf(hk, sWl[(n + 32) * 33 + k], l1);
        }
        float m = fmaxf(l0, l1);
#pragma unroll
        for (int o = 16; o > 0; o >>= 1) m = fmaxf(m, __shfl_xor_sync(FULLMASK, m, o));
        float e0 = __expf(l0 - m);
        float e1 = has1 ? __expf(l1 - m) : 0.f;
        float s = e0 + e1;
#pragma unroll
        for (int o = 16; o > 0; o >>= 1) s += __shfl_xor_sync(FULLMASK, s, o);
        float inv = 1.f / s;
        size_t ob = OFF_NOTES + ((size_t)b * TT + tau) * PP;
        out[ob + n] = e0 * inv;
        if (has1) out[ob + n + 32] = e1 * inv;
        __syncwarp();
    }
}

// ---------------- launch ----------------
extern "C" void kernel_launch(void* const* d_in, const int* in_sizes, int n_in,
                              void* d_out, int out_size) {
    const float* x    = (const float*)d_in[0];
    const float* eps  = (const float*)d_in[1];
    const float* dh0  = (const float*)d_in[2];
    const float* dc0  = (const float*)d_in[3];
    const float* eWif = (const float*)d_in[4];
    const float* eWhf = (const float*)d_in[5];
    const float* ebf  = (const float*)d_in[6];
    const float* eWib = (const float*)d_in[7];
    const float* eWhb = (const float*)d_in[8];
    const float* ebb  = (const float*)d_in[9];
    const float* Wout = (const float*)d_in[10];
    const float* bout = (const float*)d_in[11];
    const float* Wz   = (const float*)d_in[12];
    const float* bz   = (const float*)d_in[13];
    const float* cWi  = (const float*)d_in[14];
    const float* cWh  = (const float*)d_in[15];
    const float* cb   = (const float*)d_in[16];
    const float* dWi  = (const float*)d_in[17];
    const float* dWh  = (const float*)d_in[18];
    const float* db   = (const float*)d_in[19];
    const float* Wlin = (const float*)d_in[20];
    const float* blin = (const float*)d_in[21];
    float* out = (float*)d_out;

    cudaFuncSetAttribute(k_enc_persist, cudaFuncAttributeMaxDynamicSharedMemorySize, ENC_SMEM);
    cudaFuncSetAttribute(k_decoder, cudaFuncAttributeMaxDynamicSharedMemorySize, 77824);

    k_init<<<512, 256>>>();
    k_enc_persist<<<dim3(8, 8, 2), 256, ENC_SMEM>>>(x, eWif, eWhf, ebf, eWib, eWhb, ebb);
    k_wout<<<dim3(1024, 8), 256>>>(Wout, bout, out);
    k_z<<<2048, 256>>>(eps, Wz, bz, out);
    k_conductor<<<16, 1024>>>(cWi, cWh, cb, out);
    k_decoder<<<1024, 256, 77824>>>(x, dh0, dc0, dWi, dWh, db, Wlin, blin, out);
}

// round 7
// speedup vs baseline: 1.5889x; 1.1555x over previous
#include <cuda_runtime.h>
#include <math.h>

// ---------------- problem constants ----------------
#define BB   512
#define TT   256
#define HH   256
#define PP   61
#define TBARS 16
#define NPBN 16
#define LATD 512
#define DECD 32
#define KTOT (HH + PP)   // 317

// d_out layout: notes | z | mu | log_var
#define N_NOTES (BB*TT*PP)
#define N_Z     (BB*TT*DECD)
#define N_MU    (BB*TT*LATD)
#define OFF_NOTES 0
#define OFF_Z   ((size_t)N_NOTES)
#define OFF_MU  (OFF_Z + (size_t)N_Z)
#define OFF_LV  (OFF_MU + (size_t)N_MU)

#define FULLMASK 0xffffffffu

// ---------------- scratch (__device__ globals; no allocs allowed) ----------------
__device__ float g_yf[(size_t)BB*TT*HH];       // fwd encoder outputs (B,T,H)
__device__ float g_yb[(size_t)BB*TT*HH];       // bwd encoder outputs, stored un-reversed (B,T,H)
__device__ float g_h[2][2][BB*HH];             // [dir][parity]
__device__ float g_emb[BB*TBARS*DECD];         // conductor embedding (B,TB,DEC)
__device__ unsigned g_ctr[2];                  // per-direction step barrier counters

__device__ __forceinline__ float sigf(float x)   { return 1.f / (1.f + __expf(-x)); }
__device__ __forceinline__ float tanhf_(float x) { return 2.f / (1.f + __expf(-2.f * x)) - 1.f; }

__device__ __forceinline__ unsigned f2tf32(float x) {
    unsigned r;
    asm("cvt.rna.tf32.f32 %0, %1;" : "=r"(r) : "f"(x));
    return r;
}

__device__ __forceinline__ void mma_tf32(float* d, const unsigned* a, const unsigned* b) {
    asm volatile(
        "mma.sync.aligned.m16n8k8.row.col.f32.tf32.tf32.f32 "
        "{%0,%1,%2,%3}, {%4,%5,%6,%7}, {%8,%9}, {%0,%1,%2,%3};"
        : "+f"(d[0]), "+f"(d[1]), "+f"(d[2]), "+f"(d[3])
        : "r"(a[0]), "r"(a[1]), "r"(a[2]), "r"(a[3]), "r"(b[0]), "r"(b[1]));
}

// ---------------- init: zero encoder state + barrier counters ----------------
__global__ void k_init() {
    int i = blockIdx.x * blockDim.x + threadIdx.x;
    if (i < BB*HH) {
        g_h[0][0][i] = 0.f;
        g_h[1][0][i] = 0.f;
    }
    if (i < 2) g_ctr[i] = 0u;
}

// ---------------- persistent encoder: weights resident in smem, 256 steps in-kernel ----------------
#define SW_ELEMS (320 * 128)
#define SA_STRIDE 68
#define ENC_SMEM ((SW_ELEMS + 32 * SA_STRIDE) * 4)

__global__ void __launch_bounds__(256) k_enc_persist(
    const float* __restrict__ x,
    const float* __restrict__ WihF, const float* __restrict__ WhhF, const float* __restrict__ bF,
    const float* __restrict__ WihB, const float* __restrict__ WhhB, const float* __restrict__ bB)
{
    extern __shared__ float sm[];
    float* sW = sm;                 // [k 0..319][col 0..127]
    float* sA = sm + SW_ELEMS;      // [k 0..31][m 0..63] stride 68

    const int dir = blockIdx.z;
    const float* Wih  = dir ? WihB : WihF;
    const float* Whh  = dir ? WhhB : WhhF;
    const float* bias = dir ? bB   : bF;
    float* ybuf = dir ? g_yb : g_yf;

    const int tid = threadIdx.x;
    const int b0 = blockIdx.x * 64;
    const int n0 = blockIdx.y * 32;
    const int tx = tid & 15;
    const int ty = tid >> 4;

    for (int idx = tid; idx < SW_ELEMS; idx += 256) {
        int c = idx / 320;
        int k = idx - c * 320;
        int bj = (c >> 5) * HH + n0 + (c & 31);
        float v = 0.f;
        if (k < HH)        v = Whh[(size_t)bj * HH + k];
        else if (k < KTOT) v = Wih[(size_t)bj * PP + (k - HH)];
        sW[k * 128 + c] = v;
    }

    float bias_r[4][2];
#pragma unroll
    for (int g = 0; g < 4; g++)
#pragma unroll
        for (int j = 0; j < 2; j++)
            bias_r[g][j] = bias[g * HH + n0 + tx * 2 + j];

    float cst[4][2];
#pragma unroll
    for (int i = 0; i < 4; i++) { cst[i][0] = 0.f; cst[i][1] = 0.f; }

    const int lm = tid >> 2;
    const int lkq = (tid & 3) * 8;

    __syncthreads();

    volatile unsigned* vctr = &g_ctr[dir];

    for (int t = 0; t < TT; t++) {
        const int par = t & 1;
        const float* h_in  = g_h[dir][par];
        float*       h_out = g_h[dir][par ^ 1];
        const int t_x = dir ? (TT - 1 - t) : t;

        float acc[4][4][2];
#pragma unroll
        for (int g = 0; g < 4; g++)
#pragma unroll
            for (int i = 0; i < 4; i++) { acc[g][i][0] = 0.f; acc[g][i][1] = 0.f; }

        for (int ch = 0; ch < 10; ch++) {
            const int k0 = ch * 32;
            if (ch < 8) {
                const float4* p = reinterpret_cast<const float4*>(
                    h_in + (size_t)(b0 + lm) * HH + k0 + lkq);
                float4 v0 = __ldcg(p);
                float4 v1 = __ldcg(p + 1);
                float vv[8] = {v0.x, v0.y, v0.z, v0.w, v1.x, v1.y, v1.z, v1.w};
#pragma unroll
                for (int u = 0; u < 8; u++) sA[(lkq + u) * SA_STRIDE + lm] = vv[u];
            } else {
                size_t xb = ((size_t)(b0 + lm) * TT + t_x) * PP;
#pragma unroll
                for (int u = 0; u < 8; u++) {
                    int kg = k0 + lkq + u - HH;
                    sA[(lkq + u) * SA_STRIDE + lm] = (kg < PP) ? x[xb + kg] : 0.f;
                }
            }
            __syncthreads();
#pragma unroll 8
            for (int kk = 0; kk < 32; kk++) {
                float4 a4 = *reinterpret_cast<const float4*>(&sA[kk * SA_STRIDE + ty * 4]);
                float a[4] = {a4.x, a4.y, a4.z, a4.w};
                const float* wrow = &sW[(size_t)(k0 + kk) * 128];
#pragma unroll
                for (int g = 0; g < 4; g++) {
                    float2 b2 = *reinterpret_cast<const float2*>(&wrow[g * 32 + tx * 2]);
#pragma unroll
                    for (int i = 0; i < 4; i++) {
                        acc[g][i][0] = fmaf(a[i], b2.x, acc[g][i][0]);
                        acc[g][i][1] = fmaf(a[i], b2.y, acc[g][i][1]);
                    }
                }
            }
            __syncthreads();
        }

#pragma unroll
        for (int i = 0; i < 4; i++) {
            int bm = b0 + ty * 4 + i;
#pragma unroll
            for (int j = 0; j < 2; j++) {
                int n = n0 + tx * 2 + j;
                float gi = acc[0][i][j] + bias_r[0][j];
                float gf = acc[1][i][j] + bias_r[1][j];
                float gg = acc[2][i][j] + bias_r[2][j];
                float go = acc[3][i][j] + bias_r[3][j];
                float cn = sigf(gf) * cst[i][j] + sigf(gi) * tanhf_(gg);
                cst[i][j] = cn;
                float hn = sigf(go) * tanhf_(cn);
                h_out[(size_t)bm * HH + n] = hn;
                ybuf[((size_t)bm * TT + t_x) * HH + n] = hn;
            }
        }

        __threadfence();
        __syncthreads();
        if (tid == 0) {
            atomicAdd(&g_ctr[dir], 1u);
            unsigned target = (unsigned)(t + 1) * 64u;
            while (*vctr < target) { }
            __threadfence();
        }
        __syncthreads();
    }
}

// ---------------- enc @ Wout^T + bout via tf32x3 mma.sync ----------------
// M=131072, N=1024, K=512. Block 128x128, 8 warps of 64x32. grid (8, 1024)
// so all N-blocks of one A-tile are co-resident (A read from DRAM once).
#define WSTR 136

__global__ void __launch_bounds__(256) k_wout(
    const float* __restrict__ Wout, const float* __restrict__ bout,
    float* __restrict__ out)
{
    __shared__ unsigned sAh[16 * WSTR], sAl[16 * WSTR];
    __shared__ unsigned sBh[16 * WSTR], sBl[16 * WSTR];

    const int tid = threadIdx.x;
    const int lane = tid & 31, wid = tid >> 5;
    const int wm = (wid >> 2) * 64;
    const int wn = (wid & 3) * 32;
    const size_t m0 = (size_t)blockIdx.y * 128;
    const int n0 = blockIdx.x * 128;
    const int g = lane >> 2, tq = lane & 3;

    float acc[4][4][4];
#pragma unroll
    for (int mt = 0; mt < 4; mt++)
#pragma unroll
        for (int nt = 0; nt < 4; nt++)
#pragma unroll
            for (int rgi = 0; rgi < 4; rgi++) acc[mt][nt][rgi] = 0.f;

    const int lr = tid >> 1, lq = tid & 1;

    for (int kt = 0; kt < 32; kt++) {
        const float* srcA = (kt < 16) ? g_yf : g_yb;
        const int ka = (kt & 15) * 16;
        // stage A (128 rows x 16 k), hi/lo tf32 split
        {
            const float4* ap = reinterpret_cast<const float4*>(
                srcA + (m0 + lr) * HH + ka + lq * 8);
            float4 v0 = ap[0], v1 = ap[1];
            float av[8] = {v0.x, v0.y, v0.z, v0.w, v1.x, v1.y, v1.z, v1.w};
#pragma unroll
            for (int u = 0; u < 8; u++) {
                unsigned hi = f2tf32(av[u]);
                float hif = __uint_as_float(hi);
                unsigned lo = f2tf32(av[u] - hif);
                sAh[(lq * 8 + u) * WSTR + lr] = hi;
                sAl[(lq * 8 + u) * WSTR + lr] = lo;
            }
        }
        // stage B = Wout rows (128 gate-cols x 16 k)
        {
            const float4* bp = reinterpret_cast<const float4*>(
                Wout + (size_t)(n0 + lr) * 512 + kt * 16 + lq * 8);
            float4 v0 = bp[0], v1 = bp[1];
            float bv[8] = {v0.x, v0.y, v0.z, v0.w, v1.x, v1.y, v1.z, v1.w};
#pragma unroll
            for (int u = 0; u < 8; u++) {
                unsigned hi = f2tf32(bv[u]);
                float hif = __uint_as_float(hi);
                unsigned lo = f2tf32(bv[u] - hif);
                sBh[(lq * 8 + u) * WSTR + lr] = hi;
                sBl[(lq * 8 + u) * WSTR + lr] = lo;
            }
        }
        __syncthreads();

#pragma unroll
        for (int s = 0; s < 16; s += 8) {
            unsigned ah[4][4], al[4][4], bh[4][2], bl[4][2];
#pragma unroll
            for (int mt = 0; mt < 4; mt++) {
                int mb = wm + mt * 16 + g;
                ah[mt][0] = sAh[(s + tq) * WSTR + mb];
                ah[mt][1] = sAh[(s + tq) * WSTR + mb + 8];
                ah[mt][2] = sAh[(s + tq + 4) * WSTR + mb];
                ah[mt][3] = sAh[(s + tq + 4) * WSTR + mb + 8];
                al[mt][0] = sAl[(s + tq) * WSTR + mb];
                al[mt][1] = sAl[(s + tq) * WSTR + mb + 8];
                al[mt][2] = sAl[(s + tq + 4) * WSTR + mb];
                al[mt][3] = sAl[(s + tq + 4) * WSTR + mb + 8];
            }
#pragma unroll
            for (int nt = 0; nt < 4; nt++) {
                int nb = wn + nt * 8 + g;
                bh[nt][0] = sBh[(s + tq) * WSTR + nb];
                bh[nt][1] = sBh[(s + tq + 4) * WSTR + nb];
                bl[nt][0] = sBl[(s + tq) * WSTR + nb];
                bl[nt][1] = sBl[(s + tq + 4) * WSTR + nb];
            }
#pragma unroll
            for (int mt = 0; mt < 4; mt++)
#pragma unroll
                for (int nt = 0; nt < 4; nt++) {
                    mma_tf32(acc[mt][nt], ah[mt], bh[nt]);
                    mma_tf32(acc[mt][nt], al[mt], bh[nt]);
                    mma_tf32(acc[mt][nt], ah[mt], bl[nt]);
                }
        }
        __syncthreads();
    }

    // epilogue: bias + split mu / softplus(lv)
#pragma unroll
    for (int mt = 0; mt < 4; mt++) {
#pragma unroll
        for (int nt = 0; nt < 4; nt++) {
#pragma unroll
            for (int rgi = 0; rgi < 4; rgi++) {
                size_t m = m0 + wm + mt * 16 + g + ((rgi >> 1) ? 8 : 0);
                int n = n0 + wn + nt * 8 + tq * 2 + (rgi & 1);
                float v = acc[mt][nt][rgi] + bout[n];
                if (n < 512) {
                    out[OFF_MU + m * 512 + n] = v;
                } else {
                    float a2 = fabsf(v);
                    float sp = fmaxf(v, 0.f) + log1pf(__expf(-a2));
                    out[OFF_LV + m * 512 + (n - 512)] = sp;
                }
            }
        }
    }
}

// ---------------- z = (mu + eps*exp(2*lv)) @ Wz^T + bz (coalesced) ----------------
// block: 128 rows x 32 cols, thread tile 8x2, K chunks of 32.
__global__ void __launch_bounds__(256) k_z(
    const float* __restrict__ eps, const float* __restrict__ Wz, const float* __restrict__ bz,
    float* out)
{
    __shared__ float ZL[128 * 33];
    __shared__ float sWz[32 * 33];
    const int tid = threadIdx.x;
    const size_t m0 = (size_t)blockIdx.x * 128;
    const int tx = tid & 15;
    const int ty = tid >> 4;
    const float* mu = out + OFF_MU;
    const float* lv = out + OFF_LV;

    float acc[8][2];
#pragma unroll
    for (int r = 0; r < 8; r++) { acc[r][0] = 0.f; acc[r][1] = 0.f; }

    const int lr = tid >> 1, lq = tid & 1;
    const size_t rowg = m0 + lr;
    const int bidx = (int)(rowg >> 8);

    for (int kt = 0; kt < 16; kt++) {
        const int kb = kt * 32;
        // stage ZL: 128 rows x 32 k, float4 coalesced
        {
            const float4* mp = reinterpret_cast<const float4*>(mu + rowg * 512 + kb + lq * 16);
            const float4* lp = reinterpret_cast<const float4*>(lv + rowg * 512 + kb + lq * 16);
#pragma unroll
            for (int v = 0; v < 4; v++) {
                float4 m4 = mp[v];
                float4 l4 = lp[v];
                float mm[4] = {m4.x, m4.y, m4.z, m4.w};
                float ll[4] = {l4.x, l4.y, l4.z, l4.w};
#pragma unroll
                for (int u = 0; u < 4; u++) {
                    int kg = kb + lq * 16 + v * 4 + u;
                    ZL[lr * 33 + lq * 16 + v * 4 + u] =
                        mm[u] + eps[bidx * 512 + kg] * __expf(2.f * ll[u]);
                }
            }
        }
        for (int i = tid; i < 32 * 32; i += 256) {
            int col = i >> 5, k = i & 31;
            sWz[k * 33 + col] = Wz[col * 512 + kb + k];
        }
        __syncthreads();
#pragma unroll 4
        for (int kk = 0; kk < 32; kk++) {
            float w0 = sWz[kk * 33 + tx * 2];
            float w1 = sWz[kk * 33 + tx * 2 + 1];
#pragma unroll
            for (int r = 0; r < 8; r++) {
                float zv = ZL[(ty * 8 + r) * 33 + kk];
                acc[r][0] = fmaf(zv, w0, acc[r][0]);
                acc[r][1] = fmaf(zv, w1, acc[r][1]);
            }
        }
        __syncthreads();
    }
#pragma unroll
    for (int r = 0; r < 8; r++)
#pragma unroll
        for (int j = 0; j < 2; j++) {
            int n = tx * 2 + j;
            out[OFF_Z + (m0 + ty * 8 + r) * DECD + n] = acc[r][j] + bz[n];
        }
}

// ---------------- conductor LSTM: 16 steps in one kernel ----------------
__global__ void __launch_bounds__(1024) k_conductor(
    const float* __restrict__ Wih, const float* __restrict__ Whh, const float* __restrict__ bias,
    const float* __restrict__ out)
{
    __shared__ float sWi[128 * 33], sWh[128 * 33], sb[128];
    __shared__ float hs[32 * 33], zs[32 * 33];
    int tid = threadIdx.x;
    for (int i = tid; i < 128 * 32; i += 1024) {
        sWi[(i >> 5) * 33 + (i & 31)] = Wih[i];
        sWh[(i >> 5) * 33 + (i & 31)] = Whh[i];
    }
    if (tid < 128) sb[tid] = bias[tid];
    int row = tid >> 5, n = tid & 31;
    hs[row * 33 + n] = 0.f;
    float c = 0.f;
    int bglob = blockIdx.x * 32 + row;
    const float* z = out + OFF_Z;
    __syncthreads();
    for (int t = 0; t < TBARS; t++) {
        zs[row * 33 + n] = z[((size_t)bglob * TT + t) * DECD + n];
        __syncthreads();
        float a0 = sb[n], a1 = sb[32 + n], a2 = sb[64 + n], a3 = sb[96 + n];
#pragma unroll
        for (int k = 0; k < 32; k++) {
            float hk = hs[row * 33 + k], zk = zs[row * 33 + k];
            a0 = fmaf(hk, sWh[n * 33 + k],        fmaf(zk, sWi[n * 33 + k],        a0));
            a1 = fmaf(hk, sWh[(32 + n) * 33 + k], fmaf(zk, sWi[(32 + n) * 33 + k], a1));
            a2 = fmaf(hk, sWh[(64 + n) * 33 + k], fmaf(zk, sWi[(64 + n) * 33 + k], a2));
            a3 = fmaf(hk, sWh[(96 + n) * 33 + k], fmaf(zk, sWi[(96 + n) * 33 + k], a3));
        }
        c = sigf(a1) * c + sigf(a0) * tanhf_(a2);
        float h = sigf(a3) * tanhf_(c);
        __syncthreads();
        hs[row * 33 + n] = h;
        g_emb[((size_t)bglob * TBARS + t) * DECD + n] = h;
        __syncthreads();
    }
}

// ---------------- decoder: one warp per (batch, bar) row, 16 steps + softmax ----------------
__global__ void __launch_bounds__(256) k_decoder(
    const float* __restrict__ x, const float* __restrict__ dh0, const float* __restrict__ dc0,
    const float* __restrict__ Wih, const float* __restrict__ Whh, const float* __restrict__ bg,
    const float* __restrict__ Wlin, const float* __restrict__ blin, float* __restrict__ out)
{
    extern __shared__ float smdec[];
    float* sWih = smdec;              // 128*97
    float* sWhh = sWih + 128 * 97;    // 128*33
    float* sWl  = sWhh + 128 * 33;    // 64*33
    float* sbg  = sWl + 64 * 33;      // 128
    float* sbl  = sbg + 128;          // 64
    float* sx   = sbl + 64;           // 8*64
    int tid = threadIdx.x;
    for (int i = tid; i < 128 * 93; i += 256) sWih[(i / 93) * 97 + (i % 93)] = Wih[i];
    for (int i = tid; i < 128 * 32; i += 256) sWhh[(i >> 5) * 33 + (i & 31)] = Whh[i];
    for (int i = tid; i < 61 * 32;  i += 256) sWl[(i >> 5) * 33 + (i & 31)] = Wlin[i];
    if (tid < 128) sbg[tid] = bg[tid];
    if (tid < 64)  sbl[tid] = (tid < 61) ? blin[tid] : 0.f;
    __syncthreads();

    int w = tid >> 5, n = tid & 31;
    int r = blockIdx.x * 8 + w;
    int b = r >> 4, bar = r & 15;
    float h  = dh0[(size_t)bar * BB * DECD + b * DECD + n];
    float c  = dc0[(size_t)bar * BB * DECD + b * DECD + n];
    float ev = g_emb[((size_t)b * TBARS + bar) * DECD + n];
    float* xw = sx + w * 64;

    const float* w0 = sWih + (size_t)n * 97;
    const float* w1 = sWih + (size_t)(32 + n) * 97;
    const float* w2 = sWih + (size_t)(64 + n) * 97;
    const float* w3 = sWih + (size_t)(96 + n) * 97;
    const float* u0 = sWhh + (size_t)n * 33;
    const float* u1 = sWhh + (size_t)(32 + n) * 33;
    const float* u2 = sWhh + (size_t)(64 + n) * 33;
    const float* u3 = sWhh + (size_t)(96 + n) * 33;
    bool has1 = (n < 29);

    for (int t = 0; t < NPBN; t++) {
        int tau = bar * NPBN + t;
        float v0 = 0.f, v1 = 0.f;
        if (tau > 0) {
            size_t base = ((size_t)b * TT + (tau - 1)) * PP;
            v0 = x[base + n];
            if (has1) v1 = x[base + n + 32];
        }
        xw[n] = v0;
        if (has1) xw[n + 32] = v1;
        __syncwarp();

        float a0 = sbg[n], a1 = sbg[32 + n], a2 = sbg[64 + n], a3 = sbg[96 + n];
#pragma unroll
        for (int k = 0; k < 32; k++) {
            float e_ = __shfl_sync(FULLMASK, ev, k);
            a0 = fmaf(e_, w0[k], a0); a1 = fmaf(e_, w1[k], a1);
            a2 = fmaf(e_, w2[k], a2); a3 = fmaf(e_, w3[k], a3);
        }
#pragma unroll
        for (int k = 0; k < PP; k++) {
            float xv = xw[k];
            a0 = fmaf(xv, w0[32 + k], a0); a1 = fmaf(xv, w1[32 + k], a1);
            a2 = fmaf(xv, w2[32 + k], a2); a3 = fmaf(xv, w3[32 + k], a3);
        }
#pragma unroll
        for (int k = 0; k < 32; k++) {
            float hk = __shfl_sync(FULLMASK, h, k);
            a0 = fmaf(hk, u0[k], a0); a1 = fmaf(hk, u1[k], a1);
            a2 = fmaf(hk, u2[k], a2); a3 = fmaf(hk, u3[k], a3);
        }
        c = sigf(a1) * c + sigf(a0) * tanhf_(a2);
        h = sigf(a3) * tanhf_(c);

        float l0 = sbl[n];
        float l1 = has1 ? sbl[n + 32] : -1e30f;
#pragma unroll
        for (int k = 0; k < 32; k++) {
            float hk = __shfl_sync(FULLMASK, h, k);
            l0 = fmaf(hk, sWl[n * 33 + k], l0);
            if (has1) l1 = fmaf(hk, sWl[(n + 32) * 33 + k], l1);
        }
        float m = fmaxf(l0, l1);
#pragma unroll
        for (int o = 16; o > 0; o >>= 1) m = fmaxf(m, __shfl_xor_sync(FULLMASK, m, o));
        float e0 = __expf(l0 - m);
        float e1 = has1 ? __expf(l1 - m) : 0.f;
        float s = e0 + e1;
#pragma unroll
        for (int o = 16; o > 0; o >>= 1) s += __shfl_xor_sync(FULLMASK, s, o);
        float inv = 1.f / s;
        size_t ob = OFF_NOTES + ((size_t)b * TT + tau) * PP;
        out[ob + n] = e0 * inv;
        if (has1) out[ob + n + 32] = e1 * inv;
        __syncwarp();
    }
}

// ---------------- launch ----------------
extern "C" void kernel_launch(void* const* d_in, const int* in_sizes, int n_in,
                              void* d_out, int out_size) {
    const float* x    = (const float*)d_in[0];
    const float* eps  = (const float*)d_in[1];
    const float* dh0  = (const float*)d_in[2];
    const float* dc0  = (const float*)d_in[3];
    const float* eWif = (const float*)d_in[4];
    const float* eWhf = (const float*)d_in[5];
    const float* ebf  = (const float*)d_in[6];
    const float* eWib = (const float*)d_in[7];
    const float* eWhb = (const float*)d_in[8];
    const float* ebb  = (const float*)d_in[9];
    const float* Wout = (const float*)d_in[10];
    const float* bout = (const float*)d_in[11];
    const float* Wz   = (const float*)d_in[12];
    const float* bz   = (const float*)d_in[13];
    const float* cWi  = (const float*)d_in[14];
    const float* cWh  = (const float*)d_in[15];
    const float* cb   = (const float*)d_in[16];
    const float* dWi  = (const float*)d_in[17];
    const float* dWh  = (const float*)d_in[18];
    const float* db   = (const float*)d_in[19];
    const float* Wlin = (const float*)d_in[20];
    const float* blin = (const float*)d_in[21];
    float* out = (float*)d_out;

    cudaFuncSetAttribute(k_enc_persist, cudaFuncAttributeMaxDynamicSharedMemorySize, ENC_SMEM);
    cudaFuncSetAttribute(k_decoder, cudaFuncAttributeMaxDynamicSharedMemorySize, 77824);

    k_init<<<512, 256>>>();
    k_enc_persist<<<dim3(8, 8, 2), 256, ENC_SMEM>>>(x, eWif, eWhf, ebf, eWib, eWhb, ebb);
    k_wout<<<dim3(8, 1024), 256>>>(Wout, bout, out);
    k_z<<<1024, 256>>>(eps, Wz, bz, out);
    k_conductor<<<16, 1024>>>(cWi, cWh, cb, out);
    k_decoder<<<1024, 256, 77824>>>(x, dh0, dc0, dWi, dWh, db, Wlin, blin, out);
}

// round 8
// speedup vs baseline: 2.3117x; 1.4549x over previous
#include <cuda_runtime.h>
#include <cuda_fp16.h>
#include <math.h>

// ---------------- problem constants ----------------
#define BB   512
#define TT   256
#define HH   256
#define PP   61
#define TBARS 16
#define NPBN 16
#define LATD 512
#define DECD 32
#define KTOT (HH + PP)   // 317

// d_out layout: notes | z | mu | log_var
#define N_NOTES (BB*TT*PP)
#define N_Z     (BB*TT*DECD)
#define N_MU    (BB*TT*LATD)
#define OFF_NOTES 0
#define OFF_Z   ((size_t)N_NOTES)
#define OFF_MU  (OFF_Z + (size_t)N_Z)
#define OFF_LV  (OFF_MU + (size_t)N_MU)

#define FULLMASK 0xffffffffu

// ---------------- scratch (__device__ globals; no allocs allowed) ----------------
__device__ float g_yf[(size_t)BB*TT*HH];       // fwd encoder outputs (B,T,H)
__device__ float g_yb[(size_t)BB*TT*HH];       // bwd encoder outputs, stored un-reversed
__device__ float g_h[2][2][BB*HH];             // [dir][parity]
__device__ float g_emb[BB*TBARS*DECD];         // conductor embedding (B,TB,DEC)
__device__ unsigned g_ctr[2];                  // per-direction step barrier counters

__device__ __forceinline__ float sigf(float x)   { return 1.f / (1.f + __expf(-x)); }
__device__ __forceinline__ float tanhf_(float x) { return 2.f / (1.f + __expf(-2.f * x)) - 1.f; }

__device__ __forceinline__ unsigned f2tf32(float x) {
    unsigned r;
    asm("cvt.rna.tf32.f32 %0, %1;" : "=r"(r) : "f"(x));
    return r;
}

__device__ __forceinline__ void mma_tf32(float* d, const unsigned* a, const unsigned* b) {
    asm volatile(
        "mma.sync.aligned.m16n8k8.row.col.f32.tf32.tf32.f32 "
        "{%0,%1,%2,%3}, {%4,%5,%6,%7}, {%8,%9}, {%0,%1,%2,%3};"
        : "+f"(d[0]), "+f"(d[1]), "+f"(d[2]), "+f"(d[3])
        : "r"(a[0]), "r"(a[1]), "r"(a[2]), "r"(a[3]), "r"(b[0]), "r"(b[1]));
}

__device__ __forceinline__ void mma_f16(float* d, const unsigned* a, const unsigned* b) {
    asm volatile(
        "mma.sync.aligned.m16n8k16.row.col.f32.f16.f16.f32 "
        "{%0,%1,%2,%3}, {%4,%5,%6,%7}, {%8,%9}, {%0,%1,%2,%3};"
        : "+f"(d[0]), "+f"(d[1]), "+f"(d[2]), "+f"(d[3])
        : "r"(a[0]), "r"(a[1]), "r"(a[2]), "r"(a[3]), "r"(b[0]), "r"(b[1]));
}

// split fp32 -> (hi, lo) fp16 pair, packed as half2 words
__device__ __forceinline__ void split_pack(float v0, float v1, unsigned& hi2, unsigned& lo2) {
    __half h0 = __float2half_rn(v0);
    __half h1 = __float2half_rn(v1);
    __half l0 = __float2half_rn(v0 - __half2float(h0));
    __half l1 = __float2half_rn(v1 - __half2float(h1));
    __half2 hh = __halves2half2(h0, h1);
    __half2 ll = __halves2half2(l0, l1);
    hi2 = *reinterpret_cast<unsigned*>(&hh);
    lo2 = *reinterpret_cast<unsigned*>(&ll);
}

// ---------------- init: zero encoder state + barrier counters ----------------
__global__ void k_init() {
    int i = blockIdx.x * blockDim.x + threadIdx.x;
    if (i < BB*HH) {
        g_h[0][0][i] = 0.f;
        g_h[1][0][i] = 0.f;
    }
    if (i < 2) g_ctr[i] = 0u;
}

// ---------------- persistent encoder, tensor-core (fp16 hi/lo x3) ----------------
// grid (8,8,2): (batch/64, hidden/32, dir). 256 thr. Block tile 64x128, K=320.
// smem: weights hi/lo half2 [128 col][164 kpair-stride], A hi/lo half2 [64][36],
//       gate staging [64][132] f32, bias [128].
#define WKP 160
#define WSTRK 164
#define ASTR 36
#define GSTR 132
#define ENC_U32 (128*WSTRK*2 + 64*ASTR*2 + 64*GSTR + 128)
#define ENC_SMEM (ENC_U32 * 4)

__global__ void __launch_bounds__(256) k_enc_persist(
    const float* __restrict__ x,
    const float* __restrict__ WihF, const float* __restrict__ WhhF, const float* __restrict__ bF,
    const float* __restrict__ WihB, const float* __restrict__ WhhB, const float* __restrict__ bB)
{
    extern __shared__ unsigned smu[];
    unsigned* sWh = smu;                       // 128*164
    unsigned* sWl = sWh + 128*WSTRK;
    unsigned* sAh = sWl + 128*WSTRK;           // 64*36
    unsigned* sAl = sAh + 64*ASTR;
    float*    sG  = (float*)(sAl + 64*ASTR);   // 64*132
    float*    sb  = sG + 64*GSTR;              // 128

    const int dir = blockIdx.z;
    const float* Wih  = dir ? WihB : WihF;
    const float* Whh  = dir ? WhhB : WhhF;
    const float* bias = dir ? bB   : bF;
    float* ybuf = dir ? g_yb : g_yf;

    const int tid = threadIdx.x;
    const int b0 = blockIdx.x * 64;
    const int n0 = blockIdx.y * 32;
    const int lane = tid & 31;
    const int g = lane >> 2, tq = lane & 3;
    const int w = tid >> 5;
    const int wm = (w >> 2) * 32;    // 0 or 32
    const int wn = (w & 3) * 32;     // 0,32,64,96

    // ---- load + split weights into smem (once). col = nl*4 + gate ----
    for (int idx = tid; idx < 128 * WKP; idx += 256) {
        int col = idx / WKP;
        int kp  = idx - col * WKP;
        int gate = col & 3, nl = col >> 2;
        int bj = gate * HH + n0 + nl;
        int k0 = kp * 2;
        float v0 = 0.f, v1 = 0.f;
        if (k0 < HH)            v0 = Whh[(size_t)bj * HH + k0];
        else if (k0 < KTOT)     v0 = Wih[(size_t)bj * PP + (k0 - HH)];
        if (k0 + 1 < HH)        v1 = Whh[(size_t)bj * HH + k0 + 1];
        else if (k0 + 1 < KTOT) v1 = Wih[(size_t)bj * PP + (k0 + 1 - HH)];
        unsigned hi2, lo2;
        split_pack(v0, v1, hi2, lo2);
        sWh[col * WSTRK + kp] = hi2;
        sWl[col * WSTRK + kp] = lo2;
    }
    if (tid < 128) {
        int gate = tid & 3, nl = tid >> 2;
        sb[tid] = bias[gate * HH + n0 + nl];
    }

    float cst[8];
#pragma unroll
    for (int r = 0; r < 8; r++) cst[r] = 0.f;

    const int lr = tid >> 2;        // staging row 0..63
    const int lq = tid & 3;         // staging k-quarter

    __syncthreads();

    volatile unsigned* vctr = &g_ctr[dir];

    for (int t = 0; t < TT; t++) {
        const int par = t & 1;
        const float* h_in  = g_h[dir][par];
        float*       h_out = g_h[dir][par ^ 1];
        const int t_x = dir ? (TT - 1 - t) : t;

        float acc[2][4][4];
#pragma unroll
        for (int mt = 0; mt < 2; mt++)
#pragma unroll
            for (int nt = 0; nt < 4; nt++)
#pragma unroll
                for (int q = 0; q < 4; q++) acc[mt][nt][q] = 0.f;

        for (int ch = 0; ch < 5; ch++) {
            // ---- stage A chunk (64 rows x 64 k), split hi/lo ----
            float v[16];
            if (ch < 4) {
                const float4* p = reinterpret_cast<const float4*>(
                    h_in + (size_t)(b0 + lr) * HH + ch * 64 + lq * 16);
                float4 q0 = __ldcg(p), q1 = __ldcg(p + 1), q2 = __ldcg(p + 2), q3 = __ldcg(p + 3);
                v[0]=q0.x; v[1]=q0.y; v[2]=q0.z; v[3]=q0.w;
                v[4]=q1.x; v[5]=q1.y; v[6]=q1.z; v[7]=q1.w;
                v[8]=q2.x; v[9]=q2.y; v[10]=q2.z; v[11]=q2.w;
                v[12]=q3.x; v[13]=q3.y; v[14]=q3.z; v[15]=q3.w;
            } else {
                size_t xb = ((size_t)(b0 + lr) * TT + t_x) * PP;
#pragma unroll
                for (int u = 0; u < 16; u++) {
                    int c = lq * 16 + u;
                    v[u] = (c < PP) ? x[xb + c] : 0.f;
                }
            }
#pragma unroll
            for (int u = 0; u < 16; u += 2) {
                unsigned hi2, lo2;
                split_pack(v[u], v[u + 1], hi2, lo2);
                sAh[lr * ASTR + lq * 8 + (u >> 1)] = hi2;
                sAl[lr * ASTR + lq * 8 + (u >> 1)] = lo2;
            }
            __syncthreads();

            // ---- 4 k16-steps of mma ----
#pragma unroll
            for (int ks = 0; ks < 4; ks++) {
                const int kbL = ks * 8;            // local kpair
                const int kbG = ch * 32 + ks * 8;  // global kpair
                unsigned ah[2][4], al[2][4];
#pragma unroll
                for (int mt = 0; mt < 2; mt++) {
                    int r0 = (wm + mt * 16 + g) * ASTR;
                    int r1 = r0 + 8 * ASTR;
                    ah[mt][0] = sAh[r0 + kbL + tq];
                    ah[mt][1] = sAh[r1 + kbL + tq];
                    ah[mt][2] = sAh[r0 + kbL + 4 + tq];
                    ah[mt][3] = sAh[r1 + kbL + 4 + tq];
                    al[mt][0] = sAl[r0 + kbL + tq];
                    al[mt][1] = sAl[r1 + kbL + tq];
                    al[mt][2] = sAl[r0 + kbL + 4 + tq];
                    al[mt][3] = sAl[r1 + kbL + 4 + tq];
                }
                unsigned bh[4][2], bl[4][2];
#pragma unroll
                for (int nt = 0; nt < 4; nt++) {
                    int cb = (wn + nt * 8 + g) * WSTRK;
                    bh[nt][0] = sWh[cb + kbG + tq];
                    bh[nt][1] = sWh[cb + kbG + 4 + tq];
                    bl[nt][0] = sWl[cb + kbG + tq];
                    bl[nt][1] = sWl[cb + kbG + 4 + tq];
                }
#pragma unroll
                for (int mt = 0; mt < 2; mt++)
#pragma unroll
                    for (int nt = 0; nt < 4; nt++) {
                        mma_f16(acc[mt][nt], ah[mt], bh[nt]);
                        mma_f16(acc[mt][nt], al[mt], bh[nt]);
                        mma_f16(acc[mt][nt], ah[mt], bl[nt]);
                    }
            }
            __syncthreads();
        }

        // ---- stage gates to smem, then fused cell update ----
#pragma unroll
        for (int mt = 0; mt < 2; mt++) {
            int r0 = wm + mt * 16 + g;
#pragma unroll
            for (int nt = 0; nt < 4; nt++) {
                int cb = wn + nt * 8 + tq * 2;
                sG[r0 * GSTR + cb]           = acc[mt][nt][0];
                sG[r0 * GSTR + cb + 1]       = acc[mt][nt][1];
                sG[(r0 + 8) * GSTR + cb]     = acc[mt][nt][2];
                sG[(r0 + 8) * GSTR + cb + 1] = acc[mt][nt][3];
            }
        }
        __syncthreads();

#pragma unroll
        for (int r = 0; r < 8; r++) {
            int idx = tid + 256 * r;
            int m = idx >> 5, nl = idx & 31;
            float4 gq = *reinterpret_cast<const float4*>(&sG[m * GSTR + nl * 4]);
            float4 bq = *reinterpret_cast<const float4*>(&sb[nl * 4]);
            float gi = gq.x + bq.x;
            float gf = gq.y + bq.y;
            float gg = gq.z + bq.z;
            float go = gq.w + bq.w;
            float cn = sigf(gf) * cst[r] + sigf(gi) * tanhf_(gg);
            cst[r] = cn;
            float hn = sigf(go) * tanhf_(cn);
            h_out[(size_t)(b0 + m) * HH + n0 + nl] = hn;
            ybuf[((size_t)(b0 + m) * TT + t_x) * HH + n0 + nl] = hn;
        }

        // ---- grid barrier (per direction) ----
        __threadfence();
        __syncthreads();
        if (tid == 0) {
            atomicAdd(&g_ctr[dir], 1u);
            unsigned target = (unsigned)(t + 1) * 64u;
            while (*vctr < target) { }
            __threadfence();
        }
        __syncthreads();
    }
}

// ---------------- enc @ Wout^T + bout via tf32x3 mma.sync ----------------
#define WSTR 136

__global__ void __launch_bounds__(256) k_wout(
    const float* __restrict__ Wout, const float* __restrict__ bout,
    float* __restrict__ out)
{
    __shared__ unsigned sAh[16 * WSTR], sAl[16 * WSTR];
    __shared__ unsigned sBh[16 * WSTR], sBl[16 * WSTR];

    const int tid = threadIdx.x;
    const int lane = tid & 31, wid = tid >> 5;
    const int wm = (wid >> 2) * 64;
    const int wn = (wid & 3) * 32;
    const size_t m0 = (size_t)blockIdx.y * 128;
    const int n0 = blockIdx.x * 128;
    const int g = lane >> 2, tq = lane & 3;

    float acc[4][4][4];
#pragma unroll
    for (int mt = 0; mt < 4; mt++)
#pragma unroll
        for (int nt = 0; nt < 4; nt++)
#pragma unroll
            for (int rgi = 0; rgi < 4; rgi++) acc[mt][nt][rgi] = 0.f;

    const int lr = tid >> 1, lq = tid & 1;

    for (int kt = 0; kt < 32; kt++) {
        const float* srcA = (kt < 16) ? g_yf : g_yb;
        const int ka = (kt & 15) * 16;
        {
            const float4* ap = reinterpret_cast<const float4*>(
                srcA + (m0 + lr) * HH + ka + lq * 8);
            float4 v0 = ap[0], v1 = ap[1];
            float av[8] = {v0.x, v0.y, v0.z, v0.w, v1.x, v1.y, v1.z, v1.w};
#pragma unroll
            for (int u = 0; u < 8; u++) {
                unsigned hi = f2tf32(av[u]);
                float hif = __uint_as_float(hi);
                unsigned lo = f2tf32(av[u] - hif);
                sAh[(lq * 8 + u) * WSTR + lr] = hi;
                sAl[(lq * 8 + u) * WSTR + lr] = lo;
            }
        }
        {
            const float4* bp = reinterpret_cast<const float4*>(
                Wout + (size_t)(n0 + lr) * 512 + kt * 16 + lq * 8);
            float4 v0 = bp[0], v1 = bp[1];
            float bv[8] = {v0.x, v0.y, v0.z, v0.w, v1.x, v1.y, v1.z, v1.w};
#pragma unroll
            for (int u = 0; u < 8; u++) {
                unsigned hi = f2tf32(bv[u]);
                float hif = __uint_as_float(hi);
                unsigned lo = f2tf32(bv[u] - hif);
                sBh[(lq * 8 + u) * WSTR + lr] = hi;
                sBl[(lq * 8 + u) * WSTR + lr] = lo;
            }
        }
        __syncthreads();

#pragma unroll
        for (int s = 0; s < 16; s += 8) {
            unsigned ah[4][4], al[4][4], bh[4][2], bl[4][2];
#pragma unroll
            for (int mt = 0; mt < 4; mt++) {
                int mb = wm + mt * 16 + g;
                ah[mt][0] = sAh[(s + tq) * WSTR + mb];
                ah[mt][1] = sAh[(s + tq) * WSTR + mb + 8];
                ah[mt][2] = sAh[(s + tq + 4) * WSTR + mb];
                ah[mt][3] = sAh[(s + tq + 4) * WSTR + mb + 8];
                al[mt][0] = sAl[(s + tq) * WSTR + mb];
                al[mt][1] = sAl[(s + tq) * WSTR + mb + 8];
                al[mt][2] = sAl[(s + tq + 4) * WSTR + mb];
                al[mt][3] = sAl[(s + tq + 4) * WSTR + mb + 8];
            }
#pragma unroll
            for (int nt = 0; nt < 4; nt++) {
                int nb = wn + nt * 8 + g;
                bh[nt][0] = sBh[(s + tq) * WSTR + nb];
                bh[nt][1] = sBh[(s + tq + 4) * WSTR + nb];
                bl[nt][0] = sBl[(s + tq) * WSTR + nb];
                bl[nt][1] = sBl[(s + tq + 4) * WSTR + nb];
            }
#pragma unroll
            for (int mt = 0; mt < 4; mt++)
#pragma unroll
                for (int nt = 0; nt < 4; nt++) {
                    mma_tf32(acc[mt][nt], ah[mt], bh[nt]);
                    mma_tf32(acc[mt][nt], al[mt], bh[nt]);
                    mma_tf32(acc[mt][nt], ah[mt], bl[nt]);
                }
        }
        __syncthreads();
    }

#pragma unroll
    for (int mt = 0; mt < 4; mt++) {
#pragma unroll
        for (int nt = 0; nt < 4; nt++) {
#pragma unroll
            for (int rgi = 0; rgi < 4; rgi++) {
                size_t m = m0 + wm + mt * 16 + g + ((rgi >> 1) ? 8 : 0);
                int n = n0 + wn + nt * 8 + tq * 2 + (rgi & 1);
                float v = acc[mt][nt][rgi] + bout[n];
                if (n < 512) {
                    out[OFF_MU + m * 512 + n] = v;
                } else {
                    float a2 = fabsf(v);
                    float sp = fmaxf(v, 0.f) + log1pf(__expf(-a2));
                    out[OFF_LV + m * 512 + (n - 512)] = sp;
                }
            }
        }
    }
}

// ---------------- z = (mu + eps*exp(2*lv)) @ Wz^T + bz (coalesced) ----------------
__global__ void __launch_bounds__(256) k_z(
    const float* __restrict__ eps, const float* __restrict__ Wz, const float* __restrict__ bz,
    float* out)
{
    __shared__ float ZL[128 * 33];
    __shared__ float sWz[32 * 33];
    const int tid = threadIdx.x;
    const size_t m0 = (size_t)blockIdx.x * 128;
    const int tx = tid & 15;
    const int ty = tid >> 4;
    const float* mu = out + OFF_MU;
    const float* lv = out + OFF_LV;

    float acc[8][2];
#pragma unroll
    for (int r = 0; r < 8; r++) { acc[r][0] = 0.f; acc[r][1] = 0.f; }

    const int lr = tid >> 1, lq = tid & 1;
    const size_t rowg = m0 + lr;
    const int bidx = (int)(rowg >> 8);

    for (int kt = 0; kt < 16; kt++) {
        const int kb = kt * 32;
        {
            const float4* mp = reinterpret_cast<const float4*>(mu + rowg * 512 + kb + lq * 16);
            const float4* lp = reinterpret_cast<const float4*>(lv + rowg * 512 + kb + lq * 16);
#pragma unroll
            for (int v = 0; v < 4; v++) {
                float4 m4 = mp[v];
                float4 l4 = lp[v];
                float mm[4] = {m4.x, m4.y, m4.z, m4.w};
                float ll[4] = {l4.x, l4.y, l4.z, l4.w};
#pragma unroll
                for (int u = 0; u < 4; u++) {
                    int kg = kb + lq * 16 + v * 4 + u;
                    ZL[lr * 33 + lq * 16 + v * 4 + u] =
                        mm[u] + eps[bidx * 512 + kg] * __expf(2.f * ll[u]);
                }
            }
        }
        for (int i = tid; i < 32 * 32; i += 256) {
            int col = i >> 5, k = i & 31;
            sWz[k * 33 + col] = Wz[col * 512 + kb + k];
        }
        __syncthreads();
#pragma unroll 4
        for (int kk = 0; kk < 32; kk++) {
            float w0 = sWz[kk * 33 + tx * 2];
            float w1 = sWz[kk * 33 + tx * 2 + 1];
#pragma unroll
            for (int r = 0; r < 8; r++) {
                float zv = ZL[(ty * 8 + r) * 33 + kk];
                acc[r][0] = fmaf(zv, w0, acc[r][0]);
                acc[r][1] = fmaf(zv, w1, acc[r][1]);
            }
        }
        __syncthreads();
    }
#pragma unroll
    for (int r = 0; r < 8; r++)
#pragma unroll
        for (int j = 0; j < 2; j++) {
            int n = tx * 2 + j;
            out[OFF_Z + (m0 + ty * 8 + r) * DECD + n] = acc[r][j] + bz[n];
        }
}

// ---------------- conductor LSTM: 16 steps in one kernel ----------------
__global__ void __launch_bounds__(1024) k_conductor(
    const float* __restrict__ Wih, const float* __restrict__ Whh, const float* __restrict__ bias,
    const float* __restrict__ out)
{
    __shared__ float sWi[128 * 33], sWh[128 * 33], sb[128];
    __shared__ float hs[32 * 33], zs[32 * 33];
    int tid = threadIdx.x;
    for (int i = tid; i < 128 * 32; i += 1024) {
        sWi[(i >> 5) * 33 + (i & 31)] = Wih[i];
        sWh[(i >> 5) * 33 + (i & 31)] = Whh[i];
    }
    if (tid < 128) sb[tid] = bias[tid];
    int row = tid >> 5, n = tid & 31;
    hs[row * 33 + n] = 0.f;
    float c = 0.f;
    int bglob = blockIdx.x * 32 + row;
    const float* z = out + OFF_Z;
    __syncthreads();
    for (int t = 0; t < TBARS; t++) {
        zs[row * 33 + n] = z[((size_t)bglob * TT + t) * DECD + n];
        __syncthreads();
        float a0 = sb[n], a1 = sb[32 + n], a2 = sb[64 + n], a3 = sb[96 + n];
#pragma unroll
        for (int k = 0; k < 32; k++) {
            float hk = hs[row * 33 + k], zk = zs[row * 33 + k];
            a0 = fmaf(hk, sWh[n * 33 + k],        fmaf(zk, sWi[n * 33 + k],        a0));
            a1 = fmaf(hk, sWh[(32 + n) * 33 + k], fmaf(zk, sWi[(32 + n) * 33 + k], a1));
            a2 = fmaf(hk, sWh[(64 + n) * 33 + k], fmaf(zk, sWi[(64 + n) * 33 + k], a2));
            a3 = fmaf(hk, sWh[(96 + n) * 33 + k], fmaf(zk, sWi[(96 + n) * 33 + k], a3));
        }
        c = sigf(a1) * c + sigf(a0) * tanhf_(a2);
        float h = sigf(a3) * tanhf_(c);
        __syncthreads();
        hs[row * 33 + n] = h;
        g_emb[((size_t)bglob * TBARS + t) * DECD + n] = h;
        __syncthreads();
    }
}

// ---------------- decoder: one warp per (batch, bar) row, 16 steps + softmax ----------------
__global__ void __launch_bounds__(256) k_decoder(
    const float* __restrict__ x, const float* __restrict__ dh0, const float* __restrict__ dc0,
    const float* __restrict__ Wih, const float* __restrict__ Whh, const float* __restrict__ bg,
    const float* __restrict__ Wlin, const float* __restrict__ blin, float* __restrict__ out)
{
    extern __shared__ float smdec[];
    float* sWih = smdec;              // 128*97
    float* sWhh = sWih + 128 * 97;    // 128*33
    float* sWl  = sWhh + 128 * 33;    // 64*33
    float* sbg  = sWl + 64 * 33;      // 128
    float* sbl  = sbg + 128;          // 64
    float* sx   = sbl + 64;           // 8*64
    int tid = threadIdx.x;
    for (int i = tid; i < 128 * 93; i += 256) sWih[(i / 93) * 97 + (i % 93)] = Wih[i];
    for (int i = tid; i < 128 * 32; i += 256) sWhh[(i >> 5) * 33 + (i & 31)] = Whh[i];
    for (int i = tid; i < 61 * 32;  i += 256) sWl[(i >> 5) * 33 + (i & 31)] = Wlin[i];
    if (tid < 128) sbg[tid] = bg[tid];
    if (tid < 64)  sbl[tid] = (tid < 61) ? blin[tid] : 0.f;
    __syncthreads();

    int w = tid >> 5, n = tid & 31;
    int r = blockIdx.x * 8 + w;
    int b = r >> 4, bar = r & 15;
    float h  = dh0[(size_t)bar * BB * DECD + b * DECD + n];
    float c  = dc0[(size_t)bar * BB * DECD + b * DECD + n];
    float ev = g_emb[((size_t)b * TBARS + bar) * DECD + n];
    float* xw = sx + w * 64;

    const float* w0 = sWih + (size_t)n * 97;
    const float* w1 = sWih + (size_t)(32 + n) * 97;
    const float* w2 = sWih + (size_t)(64 + n) * 97;
    const float* w3 = sWih + (size_t)(96 + n) * 97;
    const float* u0 = sWhh + (size_t)n * 33;
    const float* u1 = sWhh + (size_t)(32 + n) * 33;
    const float* u2 = sWhh + (size_t)(64 + n) * 33;
    const float* u3 = sWhh + (size_t)(96 + n) * 33;
    bool has1 = (n < 29);

    for (int t = 0; t < NPBN; t++) {
        int tau = bar * NPBN + t;
        float v0 = 0.f, v1 = 0.f;
        if (tau > 0) {
            size_t base = ((size_t)b * TT + (tau - 1)) * PP;
            v0 = x[base + n];
            if (has1) v1 = x[base + n + 32];
        }
        xw[n] = v0;
        if (has1) xw[n + 32] = v1;
        __syncwarp();

        float a0 = sbg[n], a1 = sbg[32 + n], a2 = sbg[64 + n], a3 = sbg[96 + n];
#pragma unroll
        for (int k = 0; k < 32; k++) {
            float e_ = __shfl_sync(FULLMASK, ev, k);
            a0 = fmaf(e_, w0[k], a0); a1 = fmaf(e_, w1[k], a1);
            a2 = fmaf(e_, w2[k], a2); a3 = fmaf(e_, w3[k], a3);
        }
#pragma unroll
        for (int k = 0; k < PP; k++) {
            float xv = xw[k];
            a0 = fmaf(xv, w0[32 + k], a0); a1 = fmaf(xv, w1[32 + k], a1);
            a2 = fmaf(xv, w2[32 + k], a2); a3 = fmaf(xv, w3[32 + k], a3);
        }
#pragma unroll
        for (int k = 0; k < 32; k++) {
            float hk = __shfl_sync(FULLMASK, h, k);
            a0 = fmaf(hk, u0[k], a0); a1 = fmaf(hk, u1[k], a1);
            a2 = fmaf(hk, u2[k], a2); a3 = fmaf(hk, u3[k], a3);
        }
        c = sigf(a1) * c + sigf(a0) * tanhf_(a2);
        h = sigf(a3) * tanhf_(c);

        float l0 = sbl[n];
        float l1 = has1 ? sbl[n + 32] : -1e30f;
#pragma unroll
        for (int k = 0; k < 32; k++) {
            float hk = __shfl_sync(FULLMASK, h, k);
            l0 = fmaf(hk, sWl[n * 33 + k], l0);
            if (has1) l1 = fmaf(hk, sWl[(n + 32) * 33 + k], l1);
        }
        float m = fmaxf(l0, l1);
#pragma unroll
        for (int o = 16; o > 0; o >>= 1) m = fmaxf(m, __shfl_xor_sync(FULLMASK, m, o));
        float e0 = __expf(l0 - m);
        float e1 = has1 ? __expf(l1 - m) : 0.f;
        float s = e0 + e1;
#pragma unroll
        for (int o = 16; o > 0; o >>= 1) s += __shfl_xor_sync(FULLMASK, s, o);
        float inv = 1.f / s;
        size_t ob = OFF_NOTES + ((size_t)b * TT + tau) * PP;
        out[ob + n] = e0 * inv;
        if (has1) out[ob + n + 32] = e1 * inv;
        __syncwarp();
    }
}

// ---------------- launch ----------------
extern "C" void kernel_launch(void* const* d_in, const int* in_sizes, int n_in,
                              void* d_out, int out_size) {
    const float* x    = (const float*)d_in[0];
    const float* eps  = (const float*)d_in[1];
    const float* dh0  = (const float*)d_in[2];
    const float* dc0  = (const float*)d_in[3];
    const float* eWif = (const float*)d_in[4];
    const float* eWhf = (const float*)d_in[5];
    const float* ebf  = (const float*)d_in[6];
    const float* eWib = (const float*)d_in[7];
    const float* eWhb = (const float*)d_in[8];
    const float* ebb  = (const float*)d_in[9];
    const float* Wout = (const float*)d_in[10];
    const float* bout = (const float*)d_in[11];
    const float* Wz   = (const float*)d_in[12];
    const float* bz   = (const float*)d_in[13];
    const float* cWi  = (const float*)d_in[14];
    const float* cWh  = (const float*)d_in[15];
    const float* cb   = (const float*)d_in[16];
    const float* dWi  = (const float*)d_in[17];
    const float* dWh  = (const float*)d_in[18];
    const float* db   = (const float*)d_in[19];
    const float* Wlin = (const float*)d_in[20];
    const float* blin = (const float*)d_in[21];
    float* out = (float*)d_out;

    cudaFuncSetAttribute(k_enc_persist, cudaFuncAttributeMaxDynamicSharedMemorySize, ENC_SMEM);
    cudaFuncSetAttribute(k_decoder, cudaFuncAttributeMaxDynamicSharedMemorySize, 77824);

    k_init<<<512, 256>>>();
    k_enc_persist<<<dim3(8, 8, 2), 256, ENC_SMEM>>>(x, eWif, eWhf, ebf, eWib, eWhb, ebb);
    k_wout<<<dim3(8, 1024), 256>>>(Wout, bout, out);
    k_z<<<1024, 256>>>(eps, Wz, bz, out);
    k_conductor<<<16, 1024>>>(cWi, cWh, cb, out);
    k_decoder<<<1024, 256, 77824>>>(x, dh0, dc0, dWi, dWh, db, Wlin, blin, out);
}

// round 14
// speedup vs baseline: 2.3676x; 1.0242x over previous
#include <cuda_runtime.h>
#include <cuda_fp16.h>
#include <stdint.h>
#include <math.h>

// ---------------- problem constants ----------------
#define BB   512
#define TT   256
#define HH   256
#define PP   61
#define TBARS 16
#define NPBN 16
#define LATD 512
#define DECD 32
#define KTOT (HH + PP)   // 317

// d_out layout: notes | z | mu | log_var
#define N_NOTES (BB*TT*PP)
#define N_Z     (BB*TT*DECD)
#define N_MU    (BB*TT*LATD)
#define OFF_NOTES 0
#define OFF_Z   ((size_t)N_NOTES)
#define OFF_MU  (OFF_Z + (size_t)N_Z)
#define OFF_LV  (OFF_MU + (size_t)N_MU)

#define FULLMASK 0xffffffffu

// ---------------- scratch (__device__ globals; no allocs allowed) ----------------
__device__ float g_yf[(size_t)BB*TT*HH];       // fwd encoder outputs (B,T,H) fp32
__device__ float g_yb[(size_t)BB*TT*HH];       // bwd encoder outputs (un-reversed) fp32
__device__ unsigned g_hs[2][2][BB*HH];         // [dir][parity] h packed (hi fp16 | lo fp16<<16)
__device__ unsigned g_xs[(size_t)BB*TT*64];    // x packed split, padded to 64 cols
__device__ float g_emb[BB*TBARS*DECD];
__device__ unsigned g_ctr2[16];                // per-(dir,bx) group barrier counters

__device__ __forceinline__ float sigf(float x)   { return 1.f / (1.f + __expf(-x)); }
__device__ __forceinline__ float tanhf_(float x) { return 2.f / (1.f + __expf(-2.f * x)) - 1.f; }

__device__ __forceinline__ unsigned f2tf32(float x) {
    unsigned r;
    asm("cvt.rna.tf32.f32 %0, %1;" : "=r"(r) : "f"(x));
    return r;
}

__device__ __forceinline__ void mma_tf32(float* d, const unsigned* a, const unsigned* b) {
    asm volatile(
        "mma.sync.aligned.m16n8k8.row.col.f32.tf32.tf32.f32 "
        "{%0,%1,%2,%3}, {%4,%5,%6,%7}, {%8,%9}, {%0,%1,%2,%3};"
        : "+f"(d[0]), "+f"(d[1]), "+f"(d[2]), "+f"(d[3])
        : "r"(a[0]), "r"(a[1]), "r"(a[2]), "r"(a[3]), "r"(b[0]), "r"(b[1]));
}

__device__ __forceinline__ void mma_f16(float* d, const unsigned* a, const unsigned* b) {
    asm volatile(
        "mma.sync.aligned.m16n8k16.row.col.f32.f16.f16.f32 "
        "{%0,%1,%2,%3}, {%4,%5,%6,%7}, {%8,%9}, {%0,%1,%2,%3};"
        : "+f"(d[0]), "+f"(d[1]), "+f"(d[2]), "+f"(d[3])
        : "r"(a[0]), "r"(a[1]), "r"(a[2]), "r"(a[3]), "r"(b[0]), "r"(b[1]));
}

// split fp32 -> (hi, lo) fp16 pair, packed as half2 words (staging pairs)
__device__ __forceinline__ void split_pack(float v0, float v1, unsigned& hi2, unsigned& lo2) {
    __half h0 = __float2half_rn(v0);
    __half h1 = __float2half_rn(v1);
    __half l0 = __float2half_rn(v0 - __half2float(h0));
    __half l1 = __float2half_rn(v1 - __half2float(h1));
    __half2 hh = __halves2half2(h0, h1);
    __half2 ll = __halves2half2(l0, l1);
    hi2 = *reinterpret_cast<unsigned*>(&hh);
    lo2 = *reinterpret_cast<unsigned*>(&ll);
}

// pack one fp32 into (hi fp16 | lo fp16 << 16)
__device__ __forceinline__ unsigned packsplit(float v) {
    __half h = __float2half_rn(v);
    __half l = __float2half_rn(v - __half2float(h));
    return (unsigned)__half_as_ushort(h) | ((unsigned)__half_as_ushort(l) << 16);
}

// ---------------- init ----------------
__global__ void k_init() {
    int i = blockIdx.x * blockDim.x + threadIdx.x;
    if (i < BB*HH) {
        g_hs[0][0][i] = 0u;
        g_hs[1][0][i] = 0u;
    }
    if (i < 16) g_ctr2[i] = 0u;
}

// pre-split x into packed words, padded to 64 cols
__global__ void k_xsplit(const float* __restrict__ x) {
    size_t idx = (size_t)blockIdx.x * blockDim.x + threadIdx.x;
    if (idx >= (size_t)BB * TT * 64) return;
    int p = (int)(idx & 63);
    size_t bt = idx >> 6;
    float v = (p < PP) ? x[bt * PP + p] : 0.f;
    g_xs[idx] = packsplit(v);
}

// ---------------- persistent encoder (fp16 hi/lo x3 mma.sync), producer-split h ----------------
// grid (8,8,2): (batch/64, hidden/32, dir). 256 thr. Block tile 64x128, K=320.
#define WKP 160
#define WSTRK 164
#define ASTR 36
#define GSTR 132
#define ENC_U32 (128*WSTRK*2 + 64*ASTR*2 + 64*GSTR + 128)
#define ENC_SMEM (ENC_U32 * 4)

__global__ void __launch_bounds__(256) k_enc_persist(
    const float* __restrict__ WihF, const float* __restrict__ WhhF, const float* __restrict__ bF,
    const float* __restrict__ WihB, const float* __restrict__ WhhB, const float* __restrict__ bB)
{
    extern __shared__ unsigned smu[];
    unsigned* sWh = smu;                       // 128*164
    unsigned* sWl = sWh + 128*WSTRK;
    unsigned* sAh = sWl + 128*WSTRK;           // 64*36
    unsigned* sAl = sAh + 64*ASTR;
    float*    sG  = (float*)(sAl + 64*ASTR);   // 64*132
    float*    sb  = sG + 64*GSTR;              // 128

    const int dir = blockIdx.z;
    const float* Wih  = dir ? WihB : WihF;
    const float* Whh  = dir ? WhhB : WhhF;
    const float* bias = dir ? bB   : bF;
    float* ybuf = dir ? g_yb : g_yf;

    const int tid = threadIdx.x;
    const int lane = tid & 31;
    const int g = lane >> 2, tq = lane & 3;
    const int w = tid >> 5;
    const int wm = (w >> 2) * 32;    // 0 or 32
    const int wn = (w & 3) * 32;     // 0,32,64,96
    const int b0 = blockIdx.x * 64;
    const int n0 = blockIdx.y * 32;

    // ---- load + split weights into smem (once). col = nl*4 + gate ----
    for (int idx = tid; idx < 128 * WKP; idx += 256) {
        int col = idx / WKP;
        int kp  = idx - col * WKP;
        int gate = col & 3, nl = col >> 2;
        int bj = gate * HH + n0 + nl;
        int k0 = kp * 2;
        float v0 = 0.f, v1 = 0.f;
        if (k0 < HH)            v0 = Whh[(size_t)bj * HH + k0];
        else if (k0 < KTOT)     v0 = Wih[(size_t)bj * PP + (k0 - HH)];
        if (k0 + 1 < HH)        v1 = Whh[(size_t)bj * HH + k0 + 1];
        else if (k0 + 1 < KTOT) v1 = Wih[(size_t)bj * PP + (k0 + 1 - HH)];
        unsigned hi2, lo2;
        split_pack(v0, v1, hi2, lo2);
        sWh[col * WSTRK + kp] = hi2;
        sWl[col * WSTRK + kp] = lo2;
    }
    if (tid < 128) {
        int gate = tid & 3, nl = tid >> 2;
        sb[tid] = bias[gate * HH + n0 + nl];
    }

    float cst[8];
#pragma unroll
    for (int r = 0; r < 8; r++) cst[r] = 0.f;

    const int lr = tid >> 2;        // staging row 0..63
    const int lq = tid & 3;         // staging 16-word group

    __syncthreads();

    volatile unsigned* vctr = &g_ctr2[dir * 8 + blockIdx.x];

    for (int t = 0; t < TT; t++) {
        const int par = t & 1;
        const unsigned* hs_in  = g_hs[dir][par];
        unsigned*       hs_out = g_hs[dir][par ^ 1];
        const int t_x = dir ? (TT - 1 - t) : t;

        float acc[2][4][4];
#pragma unroll
        for (int mt = 0; mt < 2; mt++)
#pragma unroll
            for (int nt = 0; nt < 4; nt++)
#pragma unroll
                for (int q = 0; q < 4; q++) acc[mt][nt][q] = 0.f;

        for (int ch = 0; ch < 5; ch++) {
            // ---- stage A chunk: 64 rows x 64 k; packed words -> PRMT unzip ----
            unsigned wv[16];
            if (ch < 4) {
                const uint4* p = reinterpret_cast<const uint4*>(
                    hs_in + (size_t)(b0 + lr) * HH + ch * 64 + lq * 16);
#pragma unroll
                for (int q = 0; q < 4; q++) {
                    uint4 t4 = __ldcg(p + q);
                    wv[q*4] = t4.x; wv[q*4+1] = t4.y; wv[q*4+2] = t4.z; wv[q*4+3] = t4.w;
                }
            } else {
                const uint4* p = reinterpret_cast<const uint4*>(
                    g_xs + (((size_t)(b0 + lr) * TT + t_x) << 6) + lq * 16);
#pragma unroll
                for (int q = 0; q < 4; q++) {
                    uint4 t4 = p[q];
                    wv[q*4] = t4.x; wv[q*4+1] = t4.y; wv[q*4+2] = t4.z; wv[q*4+3] = t4.w;
                }
            }
#pragma unroll
            for (int c = 0; c < 16; c += 2) {
                unsigned hi2 = __byte_perm(wv[c], wv[c + 1], 0x5410);
                unsigned lo2 = __byte_perm(wv[c], wv[c + 1], 0x7632);
                sAh[lr * ASTR + lq * 8 + (c >> 1)] = hi2;
                sAl[lr * ASTR + lq * 8 + (c >> 1)] = lo2;
            }
            __syncthreads();

            // ---- 4 k16-steps of mma (hi*hi + lo*hi + hi*lo) ----
#pragma unroll
            for (int ks = 0; ks < 4; ks++) {
                const int kbL = ks * 8;
                const int kbG = ch * 32 + ks * 8;
                unsigned ah[2][4], al[2][4];
#pragma unroll
                for (int mt = 0; mt < 2; mt++) {
                    int r0 = (wm + mt * 16 + g) * ASTR;
                    int r1 = r0 + 8 * ASTR;
                    ah[mt][0] = sAh[r0 + kbL + tq];
                    ah[mt][1] = sAh[r1 + kbL + tq];
                    ah[mt][2] = sAh[r0 + kbL + 4 + tq];
                    ah[mt][3] = sAh[r1 + kbL + 4 + tq];
                    al[mt][0] = sAl[r0 + kbL + tq];
                    al[mt][1] = sAl[r1 + kbL + tq];
                    al[mt][2] = sAl[r0 + kbL + 4 + tq];
                    al[mt][3] = sAl[r1 + kbL + 4 + tq];
                }
                unsigned bh[4][2], bl[4][2];
#pragma unroll
                for (int nt = 0; nt < 4; nt++) {
                    int cb = (wn + nt * 8 + g) * WSTRK;
                    bh[nt][0] = sWh[cb + kbG + tq];
                    bh[nt][1] = sWh[cb + kbG + 4 + tq];
                    bl[nt][0] = sWl[cb + kbG + tq];
                    bl[nt][1] = sWl[cb + kbG + 4 + tq];
                }
#pragma unroll
                for (int mt = 0; mt < 2; mt++)
#pragma unroll
                    for (int nt = 0; nt < 4; nt++) {
                        mma_f16(acc[mt][nt], ah[mt], bh[nt]);
                        mma_f16(acc[mt][nt], al[mt], bh[nt]);
                        mma_f16(acc[mt][nt], ah[mt], bl[nt]);
                    }
            }
            __syncthreads();
        }

        // ---- stage gates to smem, then fused cell update ----
#pragma unroll
        for (int mt = 0; mt < 2; mt++) {
            int r0 = wm + mt * 16 + g;
#pragma unroll
            for (int nt = 0; nt < 4; nt++) {
                int cb = wn + nt * 8 + tq * 2;
                sG[r0 * GSTR + cb]           = acc[mt][nt][0];
                sG[r0 * GSTR + cb + 1]       = acc[mt][nt][1];
                sG[(r0 + 8) * GSTR + cb]     = acc[mt][nt][2];
                sG[(r0 + 8) * GSTR + cb + 1] = acc[mt][nt][3];
            }
        }
        __syncthreads();

#pragma unroll
        for (int r = 0; r < 8; r++) {
            int idx = tid + 256 * r;
            int m = idx >> 5, nl = idx & 31;
            float4 gq = *reinterpret_cast<const float4*>(&sG[m * GSTR + nl * 4]);
            float4 bq = *reinterpret_cast<const float4*>(&sb[nl * 4]);
            float gi = gq.x + bq.x;
            float gf = gq.y + bq.y;
            float gg = gq.z + bq.z;
            float go = gq.w + bq.w;
            float cn = sigf(gf) * cst[r] + sigf(gi) * tanhf_(gg);
            cst[r] = cn;
            float hn = sigf(go) * tanhf_(cn);
            hs_out[(size_t)(b0 + m) * HH + n0 + nl] = packsplit(hn);
            ybuf[((size_t)(b0 + m) * TT + t_x) * HH + n0 + nl] = hn;
        }

        // ---- group barrier: 8 blocks sharing (dir, bx) ----
        __threadfence();
        __syncthreads();
        if (tid == 0) {
            atomicAdd(&g_ctr2[dir * 8 + blockIdx.x], 1u);
            unsigned target = (unsigned)(t + 1) * 8u;
            while (*vctr < target) { }
            __threadfence();
        }
        __syncthreads();
    }
}

// ---------------- enc @ Wout^T + bout via tf32x3 mma.sync ----------------
#define WSTR 136

__global__ void __launch_bounds__(256) k_wout(
    const float* __restrict__ Wout, const float* __restrict__ bout,
    float* __restrict__ out)
{
    __shared__ unsigned sAh[16 * WSTR], sAl[16 * WSTR];
    __shared__ unsigned sBh[16 * WSTR], sBl[16 * WSTR];

    const int tid = threadIdx.x;
    const int lane = tid & 31, wid = tid >> 5;
    const int wm = (wid >> 2) * 64;
    const int wn = (wid & 3) * 32;
    const size_t m0 = (size_t)blockIdx.y * 128;
    const int n0 = blockIdx.x * 128;
    const int g = lane >> 2, tq = lane & 3;

    float acc[4][4][4];
#pragma unroll
    for (int mt = 0; mt < 4; mt++)
#pragma unroll
        for (int nt = 0; nt < 4; nt++)
#pragma unroll
            for (int rgi = 0; rgi < 4; rgi++) acc[mt][nt][rgi] = 0.f;

    const int lr = tid >> 1, lq = tid & 1;

    for (int kt = 0; kt < 32; kt++) {
        const float* srcA = (kt < 16) ? g_yf : g_yb;
        const int ka = (kt & 15) * 16;
        {
            const float4* ap = reinterpret_cast<const float4*>(
                srcA + (m0 + lr) * HH + ka + lq * 8);
            float4 v0 = ap[0], v1 = ap[1];
            float av[8] = {v0.x, v0.y, v0.z, v0.w, v1.x, v1.y, v1.z, v1.w};
#pragma unroll
            for (int u = 0; u < 8; u++) {
                unsigned hi = f2tf32(av[u]);
                float hif = __uint_as_float(hi);
                unsigned lo = f2tf32(av[u] - hif);
                sAh[(lq * 8 + u) * WSTR + lr] = hi;
                sAl[(lq * 8 + u) * WSTR + lr] = lo;
            }
        }
        {
            const float4* bp = reinterpret_cast<const float4*>(
                Wout + (size_t)(n0 + lr) * 512 + kt * 16 + lq * 8);
            float4 v0 = bp[0], v1 = bp[1];
            float bv[8] = {v0.x, v0.y, v0.z, v0.w, v1.x, v1.y, v1.z, v1.w};
#pragma unroll
            for (int u = 0; u < 8; u++) {
                unsigned hi = f2tf32(bv[u]);
                float hif = __uint_as_float(hi);
                unsigned lo = f2tf32(bv[u] - hif);
                sBh[(lq * 8 + u) * WSTR + lr] = hi;
                sBl[(lq * 8 + u) * WSTR + lr] = lo;
            }
        }
        __syncthreads();

#pragma unroll
        for (int s = 0; s < 16; s += 8) {
            unsigned ah[4][4], al[4][4], bh[4][2], bl[4][2];
#pragma unroll
            for (int mt = 0; mt < 4; mt++) {
                int mb = wm + mt * 16 + g;
                ah[mt][0] = sAh[(s + tq) * WSTR + mb];
                ah[mt][1] = sAh[(s + tq) * WSTR + mb + 8];
                ah[mt][2] = sAh[(s + tq + 4) * WSTR + mb];
                ah[mt][3] = sAh[(s + tq + 4) * WSTR + mb + 8];
                al[mt][0] = sAl[(s + tq) * WSTR + mb];
                al[mt][1] = sAl[(s + tq) * WSTR + mb + 8];
                al[mt][2] = sAl[(s + tq + 4) * WSTR + mb];
                al[mt][3] = sAl[(s + tq + 4) * WSTR + mb + 8];
            }
#pragma unroll
            for (int nt = 0; nt < 4; nt++) {
                int nb = wn + nt * 8 + g;
                bh[nt][0] = sBh[(s + tq) * WSTR + nb];
                bh[nt][1] = sBh[(s + tq + 4) * WSTR + nb];
                bl[nt][0] = sBl[(s + tq) * WSTR + nb];
                bl[nt][1] = sBl[(s + tq + 4) * WSTR + nb];
            }
#pragma unroll
            for (int mt = 0; mt < 4; mt++)
#pragma unroll
                for (int nt = 0; nt < 4; nt++) {
                    mma_tf32(acc[mt][nt], ah[mt], bh[nt]);
                    mma_tf32(acc[mt][nt], al[mt], bh[nt]);
                    mma_tf32(acc[mt][nt], ah[mt], bl[nt]);
                }
        }
        __syncthreads();
    }

#pragma unroll
    for (int mt = 0; mt < 4; mt++) {
#pragma unroll
        for (int nt = 0; nt < 4; nt++) {
#pragma unroll
            for (int rgi = 0; rgi < 4; rgi++) {
                size_t m = m0 + wm + mt * 16 + g + ((rgi >> 1) ? 8 : 0);
                int n = n0 + wn + nt * 8 + tq * 2 + (rgi & 1);
                float v = acc[mt][nt][rgi] + bout[n];
                if (n < 512) {
                    out[OFF_MU + m * 512 + n] = v;
                } else {
                    float a2 = fabsf(v);
                    float sp = fmaxf(v, 0.f) + log1pf(__expf(-a2));
                    out[OFF_LV + m * 512 + (n - 512)] = sp;
                }
            }
        }
    }
}

// ---------------- z = (mu + eps*exp(2*lv)) @ Wz^T + bz ----------------
__global__ void __launch_bounds__(256) k_z(
    const float* __restrict__ eps, const float* __restrict__ Wz, const float* __restrict__ bz,
    float* out)
{
    __shared__ float ZL[128 * 33];
    __shared__ float sWz[32 * 33];
    const int tid = threadIdx.x;
    const size_t m0 = (size_t)blockIdx.x * 128;
    const int tx = tid & 15;
    const int ty = tid >> 4;
    const float* mu = out + OFF_MU;
    const float* lv = out + OFF_LV;

    float acc[8][2];
#pragma unroll
    for (int r = 0; r < 8; r++) { acc[r][0] = 0.f; acc[r][1] = 0.f; }

    const int lr = tid >> 1, lq = tid & 1;
    const size_t rowg = m0 + lr;
    const int bidx = (int)(rowg >> 8);

    for (int kt = 0; kt < 16; kt++) {
        const int kb = kt * 32;
        {
            const float4* mp = reinterpret_cast<const float4*>(mu + rowg * 512 + kb + lq * 16);
            const float4* lp = reinterpret_cast<const float4*>(lv + rowg * 512 + kb + lq * 16);
#pragma unroll
            for (int v = 0; v < 4; v++) {
                float4 m4 = mp[v];
                float4 l4 = lp[v];
                float mm[4] = {m4.x, m4.y, m4.z, m4.w};
                float ll[4] = {l4.x, l4.y, l4.z, l4.w};
#pragma unroll
                for (int u = 0; u < 4; u++) {
                    int kg = kb + lq * 16 + v * 4 + u;
                    ZL[lr * 33 + lq * 16 + v * 4 + u] =
                        mm[u] + eps[bidx * 512 + kg] * __expf(2.f * ll[u]);
                }
            }
        }
        for (int i = tid; i < 32 * 32; i += 256) {
            int col = i >> 5, k = i & 31;
            sWz[k * 33 + col] = Wz[col * 512 + kb + k];
        }
        __syncthreads();
#pragma unroll 4
        for (int kk = 0; kk < 32; kk++) {
            float w0 = sWz[kk * 33 + tx * 2];
            float w1 = sWz[kk * 33 + tx * 2 + 1];
#pragma unroll
            for (int r = 0; r < 8; r++) {
                float zv = ZL[(ty * 8 + r) * 33 + kk];
                acc[r][0] = fmaf(zv, w0, acc[r][0]);
                acc[r][1] = fmaf(zv, w1, acc[r][1]);
            }
        }
        __syncthreads();
    }
#pragma unroll
    for (int r = 0; r < 8; r++)
#pragma unroll
        for (int j = 0; j < 2; j++) {
            int n = tx * 2 + j;
            out[OFF_Z + (m0 + ty * 8 + r) * DECD + n] = acc[r][j] + bz[n];
        }
}

// ---------------- conductor LSTM: 16 steps in one kernel ----------------
__global__ void __launch_bounds__(1024) k_conductor(
    const float* __restrict__ Wih, const float* __restrict__ Whh, const float* __restrict__ bias,
    const float* __restrict__ out)
{
    __shared__ float sWi[128 * 33], sWh2[128 * 33], sb[128];
    __shared__ float hs[32 * 33], zs[32 * 33];
    int tid = threadIdx.x;
    for (int i = tid; i < 128 * 32; i += 1024) {
        sWi[(i >> 5) * 33 + (i & 31)] = Wih[i];
        sWh2[(i >> 5) * 33 + (i & 31)] = Whh[i];
    }
    if (tid < 128) sb[tid] = bias[tid];
    int row = tid >> 5, n = tid & 31;
    hs[row * 33 + n] = 0.f;
    float c = 0.f;
    int bglob = blockIdx.x * 32 + row;
    const float* z = out + OFF_Z;
    __syncthreads();
    for (int t = 0; t < TBARS; t++) {
        zs[row * 33 + n] = z[((size_t)bglob * TT + t) * DECD + n];
        __syncthreads();
        float a0 = sb[n], a1 = sb[32 + n], a2 = sb[64 + n], a3 = sb[96 + n];
#pragma unroll
        for (int k = 0; k < 32; k++) {
            float hk = hs[row * 33 + k], zk = zs[row * 33 + k];
            a0 = fmaf(hk, sWh2[n * 33 + k],        fmaf(zk, sWi[n * 33 + k],        a0));
            a1 = fmaf(hk, sWh2[(32 + n) * 33 + k], fmaf(zk, sWi[(32 + n) * 33 + k], a1));
            a2 = fmaf(hk, sWh2[(64 + n) * 33 + k], fmaf(zk, sWi[(64 + n) * 33 + k], a2));
            a3 = fmaf(hk, sWh2[(96 + n) * 33 + k], fmaf(zk, sWi[(96 + n) * 33 + k], a3));
        }
        c = sigf(a1) * c + sigf(a0) * tanhf_(a2);
        float h = sigf(a3) * tanhf_(c);
        __syncthreads();
        hs[row * 33 + n] = h;
        g_emb[((size_t)bglob * TBARS + t) * DECD + n] = h;
        __syncthreads();
    }
}

// ---------------- decoder: one warp per (batch, bar) row, 16 steps + softmax ----------------
__global__ void __launch_bounds__(256) k_decoder(
    const float* __restrict__ x, const float* __restrict__ dh0, const float* __restrict__ dc0,
    const float* __restrict__ Wih, const float* __restrict__ Whh, const float* __restrict__ bg,
    const float* __restrict__ Wlin, const float* __restrict__ blin, float* __restrict__ out)
{
    extern __shared__ float smdec[];
    float* sWih = smdec;              // 128*97
    float* sWhh = sWih + 128 * 97;    // 128*33
    float* sWl  = sWhh + 128 * 33;    // 64*33
    float* sbg  = sWl + 64 * 33;      // 128
    float* sbl  = sbg + 128;          // 64
    float* sx   = sbl + 64;           // 8*64
    int tid = threadIdx.x;
    for (int i = tid; i < 128 * 93; i += 256) sWih[(i / 93) * 97 + (i % 93)] = Wih[i];
    for (int i = tid; i < 128 * 32; i += 256) sWhh[(i >> 5) * 33 + (i & 31)] = Whh[i];
    for (int i = tid; i < 61 * 32;  i += 256) sWl[(i >> 5) * 33 + (i & 31)] = Wlin[i];
    if (tid < 128) sbg[tid] = bg[tid];
    if (tid < 64)  sbl[tid] = (tid < 61) ? blin[tid] : 0.f;
    __syncthreads();

    int w = tid >> 5, n = tid & 31;
    int r = blockIdx.x * 8 + w;
    int b = r >> 4, bar = r & 15;
    float h  = dh0[(size_t)bar * BB * DECD + b * DECD + n];
    float c  = dc0[(size_t)bar * BB * DECD + b * DECD + n];
    float ev = g_emb[((size_t)b * TBARS + bar) * DECD + n];
    float* xw = sx + w * 64;

    const float* w0 = sWih + (size_t)n * 97;
    const float* w1 = sWih + (size_t)(32 + n) * 97;
    const float* w2 = sWih + (size_t)(64 + n) * 97;
    const float* w3 = sWih + (size_t)(96 + n) * 97;
    const float* u0 = sWhh + (size_t)n * 33;
    const float* u1 = sWhh + (size_t)(32 + n) * 33;
    const float* u2 = sWhh + (size_t)(64 + n) * 33;
    const float* u3 = sWhh + (size_t)(96 + n) * 33;
    bool has1 = (n < 29);

    for (int t = 0; t < NPBN; t++) {
        int tau = bar * NPBN + t;
        float v0 = 0.f, v1 = 0.f;
        if (tau > 0) {
            size_t base = ((size_t)b * TT + (tau - 1)) * PP;
            v0 = x[base + n];
            if (has1) v1 = x[base + n + 32];
        }
        xw[n] = v0;
        if (has1) xw[n + 32] = v1;
        __syncwarp();

        float a0 = sbg[n], a1 = sbg[32 + n], a2 = sbg[64 + n], a3 = sbg[96 + n];
#pragma unroll
        for (int k = 0; k < 32; k++) {
            float e_ = __shfl_sync(FULLMASK, ev, k);
            a0 = fmaf(e_, w0[k], a0); a1 = fmaf(e_, w1[k], a1);
            a2 = fmaf(e_, w2[k], a2); a3 = fmaf(e_, w3[k], a3);
        }
#pragma unroll
        for (int k = 0; k < PP; k++) {
            float xv = xw[k];
            a0 = fmaf(xv, w0[32 + k], a0); a1 = fmaf(xv, w1[32 + k], a1);
            a2 = fmaf(xv, w2[32 + k], a2); a3 = fmaf(xv, w3[32 + k], a3);
        }
#pragma unroll
        for (int k = 0; k < 32; k++) {
            float hk = __shfl_sync(FULLMASK, h, k);
            a0 = fmaf(hk, u0[k], a0); a1 = fmaf(hk, u1[k], a1);
            a2 = fmaf(hk, u2[k], a2); a3 = fmaf(hk, u3[k], a3);
        }
        c = sigf(a1) * c + sigf(a0) * tanhf_(a2);
        h = sigf(a3) * tanhf_(c);

        float l0 = sbl[n];
        float l1 = has1 ? sbl[n + 32] : -1e30f;
#pragma unroll
        for (int k = 0; k < 32; k++) {
            float hk = __shfl_sync(FULLMASK, h, k);
            l0 = fmaf(hk, sWl[n * 33 + k], l0);
            if (has1) l1 = fmaf(hk, sWl[(n + 32) * 33 + k], l1);
        }
        float m = fmaxf(l0, l1);
#pragma unroll
        for (int o = 16; o > 0; o >>= 1) m = fmaxf(m, __shfl_xor_sync(FULLMASK, m, o));
        float e0 = __expf(l0 - m);
        float e1 = has1 ? __expf(l1 - m) : 0.f;
        float s = e0 + e1;
#pragma unroll
        for (int o = 16; o > 0; o >>= 1) s += __shfl_xor_sync(FULLMASK, s, o);
        float inv = 1.f / s;
        size_t ob = OFF_NOTES + ((size_t)b * TT + tau) * PP;
        out[ob + n] = e0 * inv;
        if (has1) out[ob + n + 32] = e1 * inv;
        __syncwarp();
    }
}

// ---------------- launch ----------------
extern "C" void kernel_launch(void* const* d_in, const int* in_sizes, int n_in,
                              void* d_out, int out_size) {
    const float* x    = (const float*)d_in[0];
    const float* eps  = (const float*)d_in[1];
    const float* dh0  = (const float*)d_in[2];
    const float* dc0  = (const float*)d_in[3];
    const float* eWif = (const float*)d_in[4];
    const float* eWhf = (const float*)d_in[5];
    const float* ebf  = (const float*)d_in[6];
    const float* eWib = (const float*)d_in[7];
    const float* eWhb = (const float*)d_in[8];
    const float* ebb  = (const float*)d_in[9];
    const float* Wout = (const float*)d_in[10];
    const float* bout = (const float*)d_in[11];
    const float* Wz   = (const float*)d_in[12];
    const float* bz   = (const float*)d_in[13];
    const float* cWi  = (const float*)d_in[14];
    const float* cWh  = (const float*)d_in[15];
    const float* cb   = (const float*)d_in[16];
    const float* dWi  = (const float*)d_in[17];
    const float* dWh  = (const float*)d_in[18];
    const float* db   = (const float*)d_in[19];
    const float* Wlin = (const float*)d_in[20];
    const float* blin = (const float*)d_in[21];
    float* out = (float*)d_out;

    cudaFuncSetAttribute(k_enc_persist, cudaFuncAttributeMaxDynamicSharedMemorySize, ENC_SMEM);
    cudaFuncSetAttribute(k_decoder, cudaFuncAttributeMaxDynamicSharedMemorySize, 77824);

    k_init<<<512, 256>>>();
    k_xsplit<<<32768, 256>>>(x);
    k_enc_persist<<<dim3(8, 8, 2), 256, ENC_SMEM>>>(eWif, eWhf, ebf, eWib, eWhb, ebb);
    k_wout<<<dim3(8, 1024), 256>>>(Wout, bout, out);
    k_z<<<1024, 256>>>(eps, Wz, bz, out);
    k_conductor<<<16, 1024>>>(cWi, cWh, cb, out);
    k_decoder<<<1024, 256, 77824>>>(x, dh0, dc0, dWi, dWh, db, Wlin, blin, out);
}